// round 2
// baseline (speedup 1.0000x reference)
#include <cuda_runtime.h>
#include <math.h>

#define NB 4
#define NN 2048
#define NF 256
#define NH 512
#define NDF 256          /* H/2 */
#define NE 65536
#define ROWS (NB*NN)     /* 8192 */

// ---------------- scratch (device globals; no allocation allowed) ----------
__device__ float g_L[NN*NN];
__device__ float g_deg[NN];
__device__ float g_ew[NE];
__device__ float g_y [ROWS*NF];
__device__ float g_yi[ROWS*NF];
__device__ float g_x [ROWS*2*NF];
__device__ float g_h1[ROWS*NH];
__device__ float g_h2[ROWS*NH];
__device__ float g_dh[ROWS*NF];
__device__ float g_t [ROWS*NDF];
__device__ float g_dc[ROWS];
__device__ float g_k [6][ROWS*NF];

// ---------------- Laplacian build ------------------------------------------
__global__ void deg_init_k(float* deg){
    int i = blockIdx.x*blockDim.x + threadIdx.x;
    if (i < NN) deg[i] = 1.0f;                 // self loop contributes 1
}

__global__ void edge_k(const float* __restrict__ ea, const int* __restrict__ ei,
                       const float* __restrict__ w1, const float* __restrict__ b1,
                       const float* __restrict__ w2, const float* __restrict__ b2,
                       float* __restrict__ ew, float* __restrict__ deg){
    int e = blockIdx.x*blockDim.x + threadIdx.x;
    if (e >= NE) return;
    float a = ea[e];
    float s = b2[0];
#pragma unroll
    for (int j = 0; j < 32; j++){
        float h = fmaxf(fmaf(a, w1[j], b1[j]), 0.0f);
        s = fmaf(h, w2[j], s);
    }
    ew[e] = 1.0f/(1.0f + expf(-s));
    atomicAdd(&deg[ei[NE + e]], 1.0f);         // unweighted degree at col
}

__global__ void initL_k(float* __restrict__ L, const float* __restrict__ deg){
    int idx = blockIdx.x*blockDim.x + threadIdx.x;   // NN*NN = 4M, fits int
    int i = idx >> 11;                               // /2048
    int j = idx & (NN-1);
    float v = 0.0f;
    if (i == j){
        float dis = rsqrtf(deg[i]);
        v = 1.0f - dis*dis;                          // I - selfloop(w=1)
    }
    L[idx] = v;
}

__global__ void scatter_k(float* __restrict__ L, const float* __restrict__ deg,
                          const float* __restrict__ ew, const int* __restrict__ ei){
    int e = blockIdx.x*blockDim.x + threadIdx.x;
    if (e >= NE) return;
    int r = ei[e], c = ei[NE + e];
    float w = rsqrtf(deg[r]) * ew[e] * rsqrtf(deg[c]);
    atomicAdd(&L[r*NN + c], -w);
}

// ---------------- elementwise / small kernels ------------------------------
__global__ void concat_k(const float* __restrict__ yi, const float* __restrict__ ctx,
                         float* __restrict__ x){
    int idx = blockIdx.x*blockDim.x + threadIdx.x;   // ROWS*512
    int r = idx >> 9;
    int c = idx & 511;
    x[idx] = (c < NF) ? yi[(r<<8) + c] : ctx[((r>>11)<<8) + (c - NF)];
}

__global__ void ln_relu_k(float* __restrict__ h, const float* __restrict__ g,
                          const float* __restrict__ b){
    __shared__ float red[2][8];
    int r = blockIdx.x;
    float* row = h + (size_t)r*NH;
    int t = threadIdx.x;                   // 256 threads, 2 elems each (NH=512)
    float v0 = row[t], v1 = row[t + 256];
    float s  = v0 + v1;
    float ss = v0*v0 + v1*v1;
#pragma unroll
    for (int o = 16; o; o >>= 1){
        s  += __shfl_xor_sync(0xffffffffu, s,  o);
        ss += __shfl_xor_sync(0xffffffffu, ss, o);
    }
    if ((t & 31) == 0){ red[0][t>>5] = s; red[1][t>>5] = ss; }
    __syncthreads();
    float tot = 0.f, tot2 = 0.f;
#pragma unroll
    for (int i = 0; i < 8; i++){ tot += red[0][i]; tot2 += red[1][i]; }
    float mu  = tot  * (1.0f/NH);
    float var = tot2 * (1.0f/NH) - mu*mu;
    float is  = rsqrtf(var + 1e-5f);
    row[t]       = fmaxf(fmaf((v0-mu)*is, g[t],       b[t]),       0.0f);
    row[t + 256] = fmaxf(fmaf((v1-mu)*is, g[t + 256], b[t + 256]), 0.0f);
}

__global__ void dcoef_k(const float* __restrict__ tin, const float* __restrict__ w2,
                        const float* __restrict__ b2, float* __restrict__ dc){
    __shared__ float red[8];
    int r = blockIdx.x;
    int t = threadIdx.x;                   // 256 threads = NDF
    float s = tin[(size_t)r*NDF + t] * w2[t];
#pragma unroll
    for (int o = 16; o; o >>= 1) s += __shfl_xor_sync(0xffffffffu, s, o);
    if ((t & 31) == 0) red[t>>5] = s;
    __syncthreads();
    if (t == 0){
        float tot = 0.f;
#pragma unroll
        for (int i = 0; i < 8; i++) tot += red[i];
        dc[r] = 1.0f/(1.0f + expf(-(tot + b2[0])));
    }
}

__global__ void combine_k(float* __restrict__ out, const float* __restrict__ y,
                          float dt, int nk,
                          float c0, float c1, float c2, float c3, float c4, float c5){
    int idx = blockIdx.x*blockDim.x + threadIdx.x;
    if (idx >= ROWS*NF) return;
    float c[6] = {c0, c1, c2, c3, c4, c5};
    float v = y[idx];
    for (int i = 0; i < nk; i++) v = fmaf(dt*c[i], g_k[i][idx], v);
    out[idx] = v;
}

// ---------------- fp32 GEMM: 128x128 tile, 8x8 microtile, BK=8 -------------
// C[M,N] = A[M,K] @ B[K,N] + bias   (optional relu). All dims %128 / %8 == 0.
__global__ __launch_bounds__(256, 2) void gemm_k(
    const float* __restrict__ A, const float* __restrict__ B,
    const float* __restrict__ bias, float* __restrict__ C,
    int M, int N, int K, int relu)
{
    __shared__ float As[8][128];
    __shared__ float Bs[8][128];
    const int tid = threadIdx.x;
    const int tx = tid & 15, ty = tid >> 4;
    const int m0 = blockIdx.y << 7;
    const int n0 = blockIdx.x << 7;
    const int ar = tid >> 1, ac = (tid & 1) << 2;
    const int br = tid >> 5, bc = (tid & 31) << 2;
    const float* Ap = A + (size_t)(m0 + ar)*K + ac;
    const float* Bp = B + (size_t)br*N + n0 + bc;

    float acc[8][8];
#pragma unroll
    for (int i = 0; i < 8; i++)
#pragma unroll
        for (int j = 0; j < 8; j++) acc[i][j] = 0.0f;

    for (int k0 = 0; k0 < K; k0 += 8){
        float4 av = *(const float4*)(Ap + k0);
        As[ac+0][ar] = av.x; As[ac+1][ar] = av.y;
        As[ac+2][ar] = av.z; As[ac+3][ar] = av.w;
        *(float4*)&Bs[br][bc] = *(const float4*)(Bp + (size_t)k0*N);
        __syncthreads();
#pragma unroll
        for (int k = 0; k < 8; k++){
            float4 a0 = *(const float4*)&As[k][ty<<3];
            float4 a1 = *(const float4*)&As[k][(ty<<3) + 4];
            float4 b0 = *(const float4*)&Bs[k][tx<<3];
            float4 b1 = *(const float4*)&Bs[k][(tx<<3) + 4];
            float a[8] = {a0.x,a0.y,a0.z,a0.w,a1.x,a1.y,a1.z,a1.w};
            float b[8] = {b0.x,b0.y,b0.z,b0.w,b1.x,b1.y,b1.z,b1.w};
#pragma unroll
            for (int i = 0; i < 8; i++)
#pragma unroll
                for (int j = 0; j < 8; j++)
                    acc[i][j] = fmaf(a[i], b[j], acc[i][j]);
        }
        __syncthreads();
    }
#pragma unroll
    for (int i = 0; i < 8; i++){
        int m = m0 + (ty<<3) + i;
#pragma unroll
        for (int j = 0; j < 8; j += 4){
            int n = n0 + (tx<<3) + j;
            float4 v;
            v.x = acc[i][j+0] + bias[n+0];
            v.y = acc[i][j+1] + bias[n+1];
            v.z = acc[i][j+2] + bias[n+2];
            v.w = acc[i][j+3] + bias[n+3];
            if (relu){
                v.x = fmaxf(v.x, 0.f); v.y = fmaxf(v.y, 0.f);
                v.z = fmaxf(v.z, 0.f); v.w = fmaxf(v.w, 0.f);
            }
            *(float4*)&C[(size_t)m*N + n] = v;
        }
    }
}

// ---------------- L @ y GEMM with fused k = dhdt - dcoef*Lh epilogue --------
// per batch (blockIdx.z): Kout[bz*NN+m, n] = dhdt[...] - dc[...]*(L@Y_bz)[m,n]
__global__ __launch_bounds__(256, 2) void gemm_lh_k(
    const float* __restrict__ Lm, const float* __restrict__ Y,
    const float* __restrict__ dh, const float* __restrict__ dc,
    float* __restrict__ Kout)
{
    __shared__ float As[8][128];
    __shared__ float Bs[8][128];
    const int bz = blockIdx.z;
    const float* B = Y + (size_t)bz*NN*NF;
    const int tid = threadIdx.x;
    const int tx = tid & 15, ty = tid >> 4;
    const int m0 = blockIdx.y << 7;
    const int n0 = blockIdx.x << 7;
    const int ar = tid >> 1, ac = (tid & 1) << 2;
    const int br = tid >> 5, bc = (tid & 31) << 2;
    const float* Ap = Lm + (size_t)(m0 + ar)*NN + ac;
    const float* Bp = B  + (size_t)br*NF + n0 + bc;

    float acc[8][8];
#pragma unroll
    for (int i = 0; i < 8; i++)
#pragma unroll
        for (int j = 0; j < 8; j++) acc[i][j] = 0.0f;

    for (int k0 = 0; k0 < NN; k0 += 8){
        float4 av = *(const float4*)(Ap + k0);
        As[ac+0][ar] = av.x; As[ac+1][ar] = av.y;
        As[ac+2][ar] = av.z; As[ac+3][ar] = av.w;
        *(float4*)&Bs[br][bc] = *(const float4*)(Bp + (size_t)k0*NF);
        __syncthreads();
#pragma unroll
        for (int k = 0; k < 8; k++){
            float4 a0 = *(const float4*)&As[k][ty<<3];
            float4 a1 = *(const float4*)&As[k][(ty<<3) + 4];
            float4 b0 = *(const float4*)&Bs[k][tx<<3];
            float4 b1 = *(const float4*)&Bs[k][(tx<<3) + 4];
            float a[8] = {a0.x,a0.y,a0.z,a0.w,a1.x,a1.y,a1.z,a1.w};
            float b[8] = {b0.x,b0.y,b0.z,b0.w,b1.x,b1.y,b1.z,b1.w};
#pragma unroll
            for (int i = 0; i < 8; i++)
#pragma unroll
                for (int j = 0; j < 8; j++)
                    acc[i][j] = fmaf(a[i], b[j], acc[i][j]);
        }
        __syncthreads();
    }
#pragma unroll
    for (int i = 0; i < 8; i++){
        int m = m0 + (ty<<3) + i;
        int r = bz*NN + m;
        float d = dc[r];
#pragma unroll
        for (int j = 0; j < 8; j += 4){
            int n = n0 + (tx<<3) + j;
            float4 v;
            const float* dhp = dh + (size_t)r*NF + n;
            v.x = dhp[0] - d*acc[i][j+0];
            v.y = dhp[1] - d*acc[i][j+1];
            v.z = dhp[2] - d*acc[i][j+2];
            v.w = dhp[3] - d*acc[i][j+3];
            *(float4*)&Kout[(size_t)r*NF + n] = v;
        }
    }
}

// ---------------- host ------------------------------------------------------
static float* sym_addr(const void* s){
    void* p = nullptr;
    cudaGetSymbolAddress(&p, s);
    return (float*)p;
}

extern "C" void kernel_launch(void* const* d_in, const int* in_sizes, int n_in,
                              void* d_out, int out_size)
{
    const float* state = (const float*)d_in[0];
    const float* ctx   = (const float*)d_in[1];
    const float* ea    = (const float*)d_in[2];
    const int*   ei    = (const int*)  d_in[3];
    const float* ew_w1 = (const float*)d_in[4];
    const float* ew_b1 = (const float*)d_in[5];
    const float* ew_w2 = (const float*)d_in[6];
    const float* ew_b2 = (const float*)d_in[7];
    const float* td_w1 = (const float*)d_in[8];
    const float* td_b1 = (const float*)d_in[9];
    const float* ln1_g = (const float*)d_in[10];
    const float* ln1_b = (const float*)d_in[11];
    const float* td_w2 = (const float*)d_in[12];
    const float* td_b2 = (const float*)d_in[13];
    const float* ln2_g = (const float*)d_in[14];
    const float* ln2_b = (const float*)d_in[15];
    const float* td_w3 = (const float*)d_in[16];
    const float* td_b3 = (const float*)d_in[17];
    const float* df_w1 = (const float*)d_in[18];
    const float* df_b1 = (const float*)d_in[19];
    const float* df_w2 = (const float*)d_in[20];
    const float* df_b2 = (const float*)d_in[21];

    float* L    = sym_addr(g_L);
    float* deg  = sym_addr(g_deg);
    float* ew   = sym_addr(g_ew);
    float* y    = sym_addr(g_y);
    float* yi   = sym_addr(g_yi);
    float* x    = sym_addr(g_x);
    float* h1   = sym_addr(g_h1);
    float* h2   = sym_addr(g_h2);
    float* dh   = sym_addr(g_dh);
    float* tbuf = sym_addr(g_t);
    float* dc   = sym_addr(g_dc);
    float* kbuf = sym_addr(g_k);

    // ---- Laplacian ----
    deg_init_k<<<(NN + 255)/256, 256>>>(deg);
    edge_k<<<NE/256, 256>>>(ea, ei, ew_w1, ew_b1, ew_w2, ew_b2, ew, deg);
    initL_k<<<(NN*NN)/256, 256>>>(L, deg);
    scatter_k<<<NE/256, 256>>>(L, deg, ew, ei);

    cudaMemcpyAsync(y, state, sizeof(float)*ROWS*NF, cudaMemcpyDeviceToDevice, 0);

    auto eval_f = [&](const float* yin, int ki){
        concat_k<<<(ROWS*2*NF)/256, 256>>>(yin, ctx, x);
        gemm_k<<<dim3(NH/128, ROWS/128), 256>>>(x,  td_w1, td_b1, h1, ROWS, NH, 2*NF, 0);
        ln_relu_k<<<ROWS, 256>>>(h1, ln1_g, ln1_b);
        gemm_k<<<dim3(NH/128, ROWS/128), 256>>>(h1, td_w2, td_b2, h2, ROWS, NH, NH, 0);
        ln_relu_k<<<ROWS, 256>>>(h2, ln2_g, ln2_b);
        gemm_k<<<dim3(NF/128, ROWS/128), 256>>>(h2, td_w3, td_b3, dh, ROWS, NF, NH, 0);
        gemm_k<<<dim3(NDF/128, ROWS/128), 256>>>(yin, df_w1, df_b1, tbuf, ROWS, NDF, NF, 1);
        dcoef_k<<<ROWS, 256>>>(tbuf, df_w2, df_b2, dc);
        gemm_lh_k<<<dim3(NF/128, NN/128, NB), 256>>>(L, yin, dh, dc,
                                                     kbuf + (size_t)ki*ROWS*NF);
    };

    const float dt = 0.25f;   // (T1-T0)/N_STEPS
    const int nblk = (ROWS*NF)/256;
    for (int s = 0; s < 4; s++){
        // NOTE: k7 of dopri5 is dead (b7 == 0, no FSAL reuse in the reference)
        // so only 6 stages are evaluated.
        eval_f(y, 0);
        combine_k<<<nblk, 256>>>(yi, y, dt, 1,
            (float)(1.0/5.0), 0.f, 0.f, 0.f, 0.f, 0.f);
        eval_f(yi, 1);
        combine_k<<<nblk, 256>>>(yi, y, dt, 2,
            (float)(3.0/40.0), (float)(9.0/40.0), 0.f, 0.f, 0.f, 0.f);
        eval_f(yi, 2);
        combine_k<<<nblk, 256>>>(yi, y, dt, 3,
            (float)(44.0/45.0), (float)(-56.0/15.0), (float)(32.0/9.0), 0.f, 0.f, 0.f);
        eval_f(yi, 3);
        combine_k<<<nblk, 256>>>(yi, y, dt, 4,
            (float)(19372.0/6561.0), (float)(-25360.0/2187.0),
            (float)(64448.0/6561.0), (float)(-212.0/729.0), 0.f, 0.f);
        eval_f(yi, 4);
        combine_k<<<nblk, 256>>>(yi, y, dt, 5,
            (float)(9017.0/3168.0), (float)(-355.0/33.0),
            (float)(46732.0/5247.0), (float)(49.0/176.0),
            (float)(-5103.0/18656.0), 0.f);
        eval_f(yi, 5);
        combine_k<<<nblk, 256>>>(y, y, dt, 6,
            (float)(35.0/384.0), 0.f, (float)(500.0/1113.0),
            (float)(125.0/192.0), (float)(-2187.0/6784.0), (float)(11.0/84.0));
    }

    cudaMemcpyAsync(d_out, y, sizeof(float)*ROWS*NF, cudaMemcpyDeviceToDevice, 0);
}

// round 3
// speedup vs baseline: 1.1236x; 1.1236x over previous
#include <cuda_runtime.h>
#include <math.h>

#define NB 4
#define NN 2048
#define NF 256
#define NH 512
#define NDF 256          /* H/2 */
#define NE 65536
#define ROWS (NB*NN)     /* 8192 */

// ---------------- scratch (device globals; no allocation allowed) ----------
__device__ float g_L[NN*NN];
__device__ float g_deg[NN];
__device__ float g_ew[NE];
__device__ float g_y [ROWS*NF];
__device__ float g_yi[ROWS*NF];
__device__ float g_h1[ROWS*NH];
__device__ float g_h2[ROWS*NH];
__device__ float g_dh[ROWS*NF];
__device__ float g_t [ROWS*NDF];
__device__ float g_dc[ROWS];
__device__ float g_cb[NB*NH];
__device__ float g_k [6][ROWS*NF];

// ---------------- Laplacian build ------------------------------------------
__global__ void deg_init_k(float* deg){
    int i = blockIdx.x*blockDim.x + threadIdx.x;
    if (i < NN) deg[i] = 1.0f;                 // self loop contributes 1
}

__global__ void edge_k(const float* __restrict__ ea, const int* __restrict__ ei,
                       const float* __restrict__ w1, const float* __restrict__ b1,
                       const float* __restrict__ w2, const float* __restrict__ b2,
                       float* __restrict__ ew, float* __restrict__ deg){
    int e = blockIdx.x*blockDim.x + threadIdx.x;
    if (e >= NE) return;
    float a = ea[e];
    float s = b2[0];
#pragma unroll
    for (int j = 0; j < 32; j++){
        float h = fmaxf(fmaf(a, w1[j], b1[j]), 0.0f);
        s = fmaf(h, w2[j], s);
    }
    ew[e] = 1.0f/(1.0f + expf(-s));
    atomicAdd(&deg[ei[NE + e]], 1.0f);         // unweighted degree at col
}

__global__ void initL_k(float* __restrict__ L, const float* __restrict__ deg){
    int idx = blockIdx.x*blockDim.x + threadIdx.x;
    int i = idx >> 11;
    int j = idx & (NN-1);
    float v = 0.0f;
    if (i == j){
        float dis = rsqrtf(deg[i]);
        v = 1.0f - dis*dis;                          // I - selfloop(w=1)
    }
    L[idx] = v;
}

__global__ void scatter_k(float* __restrict__ L, const float* __restrict__ deg,
                          const float* __restrict__ ew, const int* __restrict__ ei){
    int e = blockIdx.x*blockDim.x + threadIdx.x;
    if (e >= NE) return;
    int r = ei[e], c = ei[NE + e];
    float w = rsqrtf(deg[r]) * ew[e] * rsqrtf(deg[c]);
    atomicAdd(&L[r*NN + c], -w);
}

// ---------------- ctx bias: cb[b][h] = b1[h] + ctx[b]@W1_ctx ----------------
__global__ void ctxbias_k(const float* __restrict__ ctx, const float* __restrict__ w1,
                          const float* __restrict__ b1, float* __restrict__ cb){
    int h = blockIdx.x*blockDim.x + threadIdx.x;   // [0,NH)
    int b = blockIdx.y;
    float s = b1[h];
#pragma unroll 4
    for (int f = 0; f < NF; f++)
        s = fmaf(ctx[b*NF + f], w1[(size_t)(NF + f)*NH + h], s);
    cb[b*NH + h] = s;
}

// ---------------- elementwise / small kernels ------------------------------
__global__ void ln_relu_k(float* __restrict__ h, const float* __restrict__ g,
                          const float* __restrict__ b){
    __shared__ float red[2][8];
    int r = blockIdx.x;
    float* row = h + (size_t)r*NH;
    int t = threadIdx.x;                   // 256 threads, 2 elems each (NH=512)
    float v0 = row[t], v1 = row[t + 256];
    float s  = v0 + v1;
    float ss = v0*v0 + v1*v1;
#pragma unroll
    for (int o = 16; o; o >>= 1){
        s  += __shfl_xor_sync(0xffffffffu, s,  o);
        ss += __shfl_xor_sync(0xffffffffu, ss, o);
    }
    if ((t & 31) == 0){ red[0][t>>5] = s; red[1][t>>5] = ss; }
    __syncthreads();
    float tot = 0.f, tot2 = 0.f;
#pragma unroll
    for (int i = 0; i < 8; i++){ tot += red[0][i]; tot2 += red[1][i]; }
    float mu  = tot  * (1.0f/NH);
    float var = tot2 * (1.0f/NH) - mu*mu;
    float is  = rsqrtf(var + 1e-5f);
    row[t]       = fmaxf(fmaf((v0-mu)*is, g[t],       b[t]),       0.0f);
    row[t + 256] = fmaxf(fmaf((v1-mu)*is, g[t + 256], b[t + 256]), 0.0f);
}

__global__ void dcoef_k(const float* __restrict__ tin, const float* __restrict__ w2,
                        const float* __restrict__ b2, float* __restrict__ dc){
    __shared__ float red[8];
    int r = blockIdx.x;
    int t = threadIdx.x;                   // 256 threads = NDF
    float s = tin[(size_t)r*NDF + t] * w2[t];
#pragma unroll
    for (int o = 16; o; o >>= 1) s += __shfl_xor_sync(0xffffffffu, s, o);
    if ((t & 31) == 0) red[t>>5] = s;
    __syncthreads();
    if (t == 0){
        float tot = 0.f;
#pragma unroll
        for (int i = 0; i < 8; i++) tot += red[i];
        dc[r] = 1.0f/(1.0f + expf(-(tot + b2[0])));
    }
}

__global__ void combine_k(float* __restrict__ out, const float* __restrict__ y,
                          float dt, int nk,
                          float c0, float c1, float c2, float c3, float c4, float c5){
    int idx = blockIdx.x*blockDim.x + threadIdx.x;
    if (idx >= ROWS*NF) return;
    float c[6] = {c0, c1, c2, c3, c4, c5};
    float v = y[idx];
    for (int i = 0; i < nk; i++) v = fmaf(dt*c[i], g_k[i][idx], v);
    out[idx] = v;
}

// ---------------- fp32 GEMM: 128x128 tile, BK=16, double-buffered ----------
// C[M,N] = A[M,K] @ B[K,N] + bias[batch(m)*bstride + n]   (optional relu)
// dims: M%128==0, N%128==0, K%16==0. batch(m) = m>>11.
__global__ __launch_bounds__(256, 2) void gemm_k2(
    const float* __restrict__ A, const float* __restrict__ B,
    const float* __restrict__ bias, int bstride, float* __restrict__ C,
    int M, int N, int K, int relu)
{
    __shared__ float As[2][16][128];
    __shared__ float Bs[2][16][128];
    const int tid = threadIdx.x;
    const int tx = tid & 15, ty = tid >> 4;
    const int m0 = blockIdx.y << 7, n0 = blockIdx.x << 7;
    const int ar = tid >> 1, ac = (tid & 1) << 3;     // A: 128 rows, 2 thr/row, 8 floats each
    const int br = tid >> 4, bc = (tid & 15) << 2;    // B: 16 rows, 2 float4/thr (bc, bc+64)
    const float* Ap = A + (size_t)(m0 + ar)*K + ac;
    const float* Bp = B + (size_t)br*N + n0 + bc;

    float4 pa0, pa1, pb0, pb1;
    // preload tile 0
    pa0 = *(const float4*)(Ap);     pa1 = *(const float4*)(Ap + 4);
    pb0 = *(const float4*)(Bp);     pb1 = *(const float4*)(Bp + 64);
    As[0][ac+0][ar]=pa0.x; As[0][ac+1][ar]=pa0.y; As[0][ac+2][ar]=pa0.z; As[0][ac+3][ar]=pa0.w;
    As[0][ac+4][ar]=pa1.x; As[0][ac+5][ar]=pa1.y; As[0][ac+6][ar]=pa1.z; As[0][ac+7][ar]=pa1.w;
    *(float4*)&Bs[0][br][bc]      = pb0;
    *(float4*)&Bs[0][br][bc + 64] = pb1;
    __syncthreads();

    float acc[8][8];
#pragma unroll
    for (int i = 0; i < 8; i++)
#pragma unroll
        for (int j = 0; j < 8; j++) acc[i][j] = 0.0f;

    int buf = 0;
    for (int k0 = 16; k0 < K; k0 += 16){
        // prefetch next tile (LDG overlaps with the 16-step compute below)
        pa0 = *(const float4*)(Ap + k0);     pa1 = *(const float4*)(Ap + k0 + 4);
        pb0 = *(const float4*)(Bp + (size_t)k0*N);
        pb1 = *(const float4*)(Bp + (size_t)k0*N + 64);
#pragma unroll
        for (int k = 0; k < 16; k++){
            float4 a0 = *(const float4*)&As[buf][k][ty<<3];
            float4 a1 = *(const float4*)&As[buf][k][(ty<<3) + 4];
            float4 b0 = *(const float4*)&Bs[buf][k][tx<<3];
            float4 b1 = *(const float4*)&Bs[buf][k][(tx<<3) + 4];
            float a[8] = {a0.x,a0.y,a0.z,a0.w,a1.x,a1.y,a1.z,a1.w};
            float b[8] = {b0.x,b0.y,b0.z,b0.w,b1.x,b1.y,b1.z,b1.w};
#pragma unroll
            for (int i = 0; i < 8; i++)
#pragma unroll
                for (int j = 0; j < 8; j++)
                    acc[i][j] = fmaf(a[i], b[j], acc[i][j]);
        }
        int nb = buf ^ 1;
        As[nb][ac+0][ar]=pa0.x; As[nb][ac+1][ar]=pa0.y; As[nb][ac+2][ar]=pa0.z; As[nb][ac+3][ar]=pa0.w;
        As[nb][ac+4][ar]=pa1.x; As[nb][ac+5][ar]=pa1.y; As[nb][ac+6][ar]=pa1.z; As[nb][ac+7][ar]=pa1.w;
        *(float4*)&Bs[nb][br][bc]      = pb0;
        *(float4*)&Bs[nb][br][bc + 64] = pb1;
        __syncthreads();
        buf = nb;
    }
    // last tile
#pragma unroll
    for (int k = 0; k < 16; k++){
        float4 a0 = *(const float4*)&As[buf][k][ty<<3];
        float4 a1 = *(const float4*)&As[buf][k][(ty<<3) + 4];
        float4 b0 = *(const float4*)&Bs[buf][k][tx<<3];
        float4 b1 = *(const float4*)&Bs[buf][k][(tx<<3) + 4];
        float a[8] = {a0.x,a0.y,a0.z,a0.w,a1.x,a1.y,a1.z,a1.w};
        float b[8] = {b0.x,b0.y,b0.z,b0.w,b1.x,b1.y,b1.z,b1.w};
#pragma unroll
        for (int i = 0; i < 8; i++)
#pragma unroll
            for (int j = 0; j < 8; j++)
                acc[i][j] = fmaf(a[i], b[j], acc[i][j]);
    }

    const float* bp = bias + (size_t)(m0 >> 11)*bstride;
#pragma unroll
    for (int i = 0; i < 8; i++){
        int m = m0 + (ty<<3) + i;
#pragma unroll
        for (int j = 0; j < 8; j += 4){
            int n = n0 + (tx<<3) + j;
            float4 v;
            v.x = acc[i][j+0] + bp[n+0];
            v.y = acc[i][j+1] + bp[n+1];
            v.z = acc[i][j+2] + bp[n+2];
            v.w = acc[i][j+3] + bp[n+3];
            if (relu){
                v.x = fmaxf(v.x, 0.f); v.y = fmaxf(v.y, 0.f);
                v.z = fmaxf(v.z, 0.f); v.w = fmaxf(v.w, 0.f);
            }
            *(float4*)&C[(size_t)m*N + n] = v;
        }
    }
}

// ---------------- L @ y GEMM, 64x128 tile, fused k = dhdt - dcoef*Lh --------
// grid (NF/128, NN/64, NB); per batch bz: Kout[r,n] = dh[r,n] - dc[r]*(L@Y_bz)[m,n]
__global__ __launch_bounds__(256, 2) void gemm_lh2(
    const float* __restrict__ Lm, const float* __restrict__ Y,
    const float* __restrict__ dh, const float* __restrict__ dc,
    float* __restrict__ Kout)
{
    __shared__ float As[2][16][64];
    __shared__ float Bs[2][16][128];
    const int bz = blockIdx.z;
    const float* B = Y + (size_t)bz*NN*NF;
    const int tid = threadIdx.x;
    const int tx = tid & 15, ty = tid >> 4;
    const int m0 = blockIdx.y << 6, n0 = blockIdx.x << 7;
    const int ar = tid >> 2, ac = (tid & 3) << 2;     // A: 64 rows, 4 thr/row, 4 floats each
    const int br = tid >> 4, bc = (tid & 15) << 2;
    const float* Ap = Lm + (size_t)(m0 + ar)*NN + ac;
    const float* Bp = B  + (size_t)br*NF + n0 + bc;

    float4 pa, pb0, pb1;
    pa  = *(const float4*)(Ap);
    pb0 = *(const float4*)(Bp);
    pb1 = *(const float4*)(Bp + 64);
    As[0][ac+0][ar]=pa.x; As[0][ac+1][ar]=pa.y; As[0][ac+2][ar]=pa.z; As[0][ac+3][ar]=pa.w;
    *(float4*)&Bs[0][br][bc]      = pb0;
    *(float4*)&Bs[0][br][bc + 64] = pb1;
    __syncthreads();

    float acc[4][8];
#pragma unroll
    for (int i = 0; i < 4; i++)
#pragma unroll
        for (int j = 0; j < 8; j++) acc[i][j] = 0.0f;

    int buf = 0;
    for (int k0 = 16; k0 < NN; k0 += 16){
        pa  = *(const float4*)(Ap + k0);
        pb0 = *(const float4*)(Bp + (size_t)k0*NF);
        pb1 = *(const float4*)(Bp + (size_t)k0*NF + 64);
#pragma unroll
        for (int k = 0; k < 16; k++){
            float4 av = *(const float4*)&As[buf][k][ty<<2];
            float4 b0 = *(const float4*)&Bs[buf][k][tx<<3];
            float4 b1 = *(const float4*)&Bs[buf][k][(tx<<3) + 4];
            float a[4] = {av.x,av.y,av.z,av.w};
            float b[8] = {b0.x,b0.y,b0.z,b0.w,b1.x,b1.y,b1.z,b1.w};
#pragma unroll
            for (int i = 0; i < 4; i++)
#pragma unroll
                for (int j = 0; j < 8; j++)
                    acc[i][j] = fmaf(a[i], b[j], acc[i][j]);
        }
        int nb = buf ^ 1;
        As[nb][ac+0][ar]=pa.x; As[nb][ac+1][ar]=pa.y; As[nb][ac+2][ar]=pa.z; As[nb][ac+3][ar]=pa.w;
        *(float4*)&Bs[nb][br][bc]      = pb0;
        *(float4*)&Bs[nb][br][bc + 64] = pb1;
        __syncthreads();
        buf = nb;
    }
#pragma unroll
    for (int k = 0; k < 16; k++){
        float4 av = *(const float4*)&As[buf][k][ty<<2];
        float4 b0 = *(const float4*)&Bs[buf][k][tx<<3];
        float4 b1 = *(const float4*)&Bs[buf][k][(tx<<3) + 4];
        float a[4] = {av.x,av.y,av.z,av.w};
        float b[8] = {b0.x,b0.y,b0.z,b0.w,b1.x,b1.y,b1.z,b1.w};
#pragma unroll
        for (int i = 0; i < 4; i++)
#pragma unroll
            for (int j = 0; j < 8; j++)
                acc[i][j] = fmaf(a[i], b[j], acc[i][j]);
    }

#pragma unroll
    for (int i = 0; i < 4; i++){
        int m = m0 + (ty<<2) + i;
        int r = bz*NN + m;
        float d = dc[r];
#pragma unroll
        for (int j = 0; j < 8; j += 4){
            int n = n0 + (tx<<3) + j;
            const float* dhp = dh + (size_t)r*NF + n;
            float4 v;
            v.x = dhp[0] - d*acc[i][j+0];
            v.y = dhp[1] - d*acc[i][j+1];
            v.z = dhp[2] - d*acc[i][j+2];
            v.w = dhp[3] - d*acc[i][j+3];
            *(float4*)&Kout[(size_t)r*NF + n] = v;
        }
    }
}

// ---------------- host ------------------------------------------------------
static float* sym_addr(const void* s){
    void* p = nullptr;
    cudaGetSymbolAddress(&p, s);
    return (float*)p;
}

extern "C" void kernel_launch(void* const* d_in, const int* in_sizes, int n_in,
                              void* d_out, int out_size)
{
    const float* state = (const float*)d_in[0];
    const float* ctx   = (const float*)d_in[1];
    const float* ea    = (const float*)d_in[2];
    const int*   ei    = (const int*)  d_in[3];
    const float* ew_w1 = (const float*)d_in[4];
    const float* ew_b1 = (const float*)d_in[5];
    const float* ew_w2 = (const float*)d_in[6];
    const float* ew_b2 = (const float*)d_in[7];
    const float* td_w1 = (const float*)d_in[8];
    const float* td_b1 = (const float*)d_in[9];
    const float* ln1_g = (const float*)d_in[10];
    const float* ln1_b = (const float*)d_in[11];
    const float* td_w2 = (const float*)d_in[12];
    const float* td_b2 = (const float*)d_in[13];
    const float* ln2_g = (const float*)d_in[14];
    const float* ln2_b = (const float*)d_in[15];
    const float* td_w3 = (const float*)d_in[16];
    const float* td_b3 = (const float*)d_in[17];
    const float* df_w1 = (const float*)d_in[18];
    const float* df_b1 = (const float*)d_in[19];
    const float* df_w2 = (const float*)d_in[20];
    const float* df_b2 = (const float*)d_in[21];

    float* L    = sym_addr(g_L);
    float* deg  = sym_addr(g_deg);
    float* ew   = sym_addr(g_ew);
    float* y    = sym_addr(g_y);
    float* yi   = sym_addr(g_yi);
    float* h1   = sym_addr(g_h1);
    float* h2   = sym_addr(g_h2);
    float* dh   = sym_addr(g_dh);
    float* tbuf = sym_addr(g_t);
    float* dc   = sym_addr(g_dc);
    float* cb   = sym_addr(g_cb);
    float* kbuf = sym_addr(g_k);

    // ---- Laplacian ----
    deg_init_k<<<(NN + 255)/256, 256>>>(deg);
    edge_k<<<NE/256, 256>>>(ea, ei, ew_w1, ew_b1, ew_w2, ew_b2, ew, deg);
    initL_k<<<(NN*NN)/256, 256>>>(L, deg);
    scatter_k<<<NE/256, 256>>>(L, deg, ew, ei);

    // ---- ctx contribution to layer-1 preactivation (constant across evals) --
    ctxbias_k<<<dim3(NH/128, NB), 128>>>(ctx, td_w1, td_b1, cb);

    cudaMemcpyAsync(y, state, sizeof(float)*ROWS*NF, cudaMemcpyDeviceToDevice, 0);

    auto eval_f = [&](const float* yin, int ki){
        // layer1: yin @ W1_state + cbias[batch]   (ctx half folded into cbias)
        gemm_k2<<<dim3(NH/128, ROWS/128), 256>>>(yin, td_w1, cb, NH, h1, ROWS, NH, NF, 0);
        ln_relu_k<<<ROWS, 256>>>(h1, ln1_g, ln1_b);
        gemm_k2<<<dim3(NH/128, ROWS/128), 256>>>(h1, td_w2, td_b2, 0, h2, ROWS, NH, NH, 0);
        ln_relu_k<<<ROWS, 256>>>(h2, ln2_g, ln2_b);
        gemm_k2<<<dim3(NF/128, ROWS/128), 256>>>(h2, td_w3, td_b3, 0, dh, ROWS, NF, NH, 0);
        gemm_k2<<<dim3(NDF/128, ROWS/128), 256>>>(yin, df_w1, df_b1, 0, tbuf, ROWS, NDF, NF, 1);
        dcoef_k<<<ROWS, 256>>>(tbuf, df_w2, df_b2, dc);
        gemm_lh2<<<dim3(NF/128, NN/64, NB), 256>>>(L, yin, dh, dc,
                                                   kbuf + (size_t)ki*ROWS*NF);
    };

    const float dt = 0.25f;   // (T1-T0)/N_STEPS
    const int nblk = (ROWS*NF)/256;
    for (int s = 0; s < 4; s++){
        // k7 of dopri5 is dead (b7 == 0, no FSAL reuse) -> 6 stages only
        eval_f(y, 0);
        combine_k<<<nblk, 256>>>(yi, y, dt, 1,
            (float)(1.0/5.0), 0.f, 0.f, 0.f, 0.f, 0.f);
        eval_f(yi, 1);
        combine_k<<<nblk, 256>>>(yi, y, dt, 2,
            (float)(3.0/40.0), (float)(9.0/40.0), 0.f, 0.f, 0.f, 0.f);
        eval_f(yi, 2);
        combine_k<<<nblk, 256>>>(yi, y, dt, 3,
            (float)(44.0/45.0), (float)(-56.0/15.0), (float)(32.0/9.0), 0.f, 0.f, 0.f);
        eval_f(yi, 3);
        combine_k<<<nblk, 256>>>(yi, y, dt, 4,
            (float)(19372.0/6561.0), (float)(-25360.0/2187.0),
            (float)(64448.0/6561.0), (float)(-212.0/729.0), 0.f, 0.f);
        eval_f(yi, 4);
        combine_k<<<nblk, 256>>>(yi, y, dt, 5,
            (float)(9017.0/3168.0), (float)(-355.0/33.0),
            (float)(46732.0/5247.0), (float)(49.0/176.0),
            (float)(-5103.0/18656.0), 0.f);
        eval_f(yi, 5);
        combine_k<<<nblk, 256>>>(y, y, dt, 6,
            (float)(35.0/384.0), 0.f, (float)(500.0/1113.0),
            (float)(125.0/192.0), (float)(-2187.0/6784.0), (float)(11.0/84.0));
    }

    cudaMemcpyAsync(d_out, y, sizeof(float)*ROWS*NF, cudaMemcpyDeviceToDevice, 0);
}

// round 7
// speedup vs baseline: 1.9932x; 1.7740x over previous
#include <cuda_runtime.h>
#include <cuda_bf16.h>
#include <math.h>
#include <stdint.h>

#define NB 4
#define NN 2048
#define NF 256
#define NH 512
#define NDF 256          /* H/2 */
#define NE 65536
#define ROWS (NB*NN)     /* 8192 */

// ---------------- fp32 scratch ----------------------------------------------
__device__ float g_L[NN*NN];
__device__ float g_deg[NN];
__device__ float g_ew[NE];
__device__ float g_y [ROWS*NF];
__device__ float g_yi[ROWS*NF];
__device__ float g_h1[ROWS*NH];
__device__ float g_h2[ROWS*NH];
__device__ float g_dh[ROWS*NF];
__device__ float g_t [ROWS*NDF];
__device__ float g_dc[ROWS];
__device__ float g_cb[NB*NH];
__device__ float g_k [6][ROWS*NF];
// ---------------- bf16 split operands ---------------------------------------
__device__ __nv_bfloat16 g_Lbh[NN*NN],  g_Lbl[NN*NN];      // L (A side) [M,K]
__device__ __nv_bfloat16 g_w1h[NH*NF],  g_w1l[NH*NF];      // W1_state^T [N,K]
__device__ __nv_bfloat16 g_w2h[NH*NH],  g_w2l[NH*NH];      // W2^T
__device__ __nv_bfloat16 g_w3h[NF*NH],  g_w3l[NF*NH];      // W3^T
__device__ __nv_bfloat16 g_dwh[NDF*NF], g_dwl[NDF*NF];     // df_w1^T
__device__ __nv_bfloat16 g_yh[ROWS*NF], g_yl[ROWS*NF];     // yin  (A side)
__device__ __nv_bfloat16 g_yth[NB*NF*NN], g_ytl[NB*NF*NN]; // yin^T per batch (B side)
__device__ __nv_bfloat16 g_ah[ROWS*NH], g_al[ROWS*NH];     // h1/h2 split (A side)

// ---------------- Laplacian build --------------------------------------------
__global__ void deg_init_k(float* deg){
    int i = blockIdx.x*blockDim.x + threadIdx.x;
    if (i < NN) deg[i] = 1.0f;
}
__global__ void edge_k(const float* __restrict__ ea, const int* __restrict__ ei,
                       const float* __restrict__ w1, const float* __restrict__ b1,
                       const float* __restrict__ w2, const float* __restrict__ b2,
                       float* __restrict__ ew, float* __restrict__ deg){
    int e = blockIdx.x*blockDim.x + threadIdx.x;
    if (e >= NE) return;
    float a = ea[e];
    float s = b2[0];
#pragma unroll
    for (int j = 0; j < 32; j++){
        float h = fmaxf(fmaf(a, w1[j], b1[j]), 0.0f);
        s = fmaf(h, w2[j], s);
    }
    ew[e] = 1.0f/(1.0f + expf(-s));
    atomicAdd(&deg[ei[NE + e]], 1.0f);
}
__global__ void initL_k(float* __restrict__ L, const float* __restrict__ deg){
    int idx = blockIdx.x*blockDim.x + threadIdx.x;
    int i = idx >> 11, j = idx & (NN-1);
    float v = 0.0f;
    if (i == j){
        float dis = rsqrtf(deg[i]);
        v = 1.0f - dis*dis;
    }
    L[idx] = v;
}
__global__ void scatter_k(float* __restrict__ L, const float* __restrict__ deg,
                          const float* __restrict__ ew, const int* __restrict__ ei){
    int e = blockIdx.x*blockDim.x + threadIdx.x;
    if (e >= NE) return;
    int r = ei[e], c = ei[NE + e];
    float w = rsqrtf(deg[r]) * ew[e] * rsqrtf(deg[c]);
    atomicAdd(&L[r*NN + c], -w);
}
__global__ void ctxbias_k(const float* __restrict__ ctx, const float* __restrict__ w1,
                          const float* __restrict__ b1, float* __restrict__ cb){
    int h = blockIdx.x*blockDim.x + threadIdx.x;
    int b = blockIdx.y;
    float s = b1[h];
#pragma unroll 4
    for (int f = 0; f < NF; f++)
        s = fmaf(ctx[b*NF + f], w1[(size_t)(NF + f)*NH + h], s);
    cb[b*NH + h] = s;
}

// ---------------- split / transpose-split ------------------------------------
__global__ void split_k(const float* __restrict__ x, __nv_bfloat16* __restrict__ hi,
                        __nv_bfloat16* __restrict__ lo, int n){
    int i = blockIdx.x*blockDim.x + threadIdx.x;
    if (i >= n) return;
    float v = x[i];
    __nv_bfloat16 h = __float2bfloat16(v);
    hi[i] = h;
    lo[i] = __float2bfloat16(v - __bfloat162float(h));
}
// out[z][c][r] = x[z*zx + r*ldx + c]; grid (C/32, R/32, Z), block (32,8)
__global__ void tsplit_k(const float* __restrict__ x, int ldx,
                         size_t zx, size_t zo, int R,
                         __nv_bfloat16* __restrict__ hi, __nv_bfloat16* __restrict__ lo){
    __shared__ float t[32][33];
    const float* xp = x + blockIdx.z*zx;
    __nv_bfloat16* hp = hi + blockIdx.z*zo;
    __nv_bfloat16* lp = lo + blockIdx.z*zo;
    int c0 = blockIdx.x<<5, r0 = blockIdx.y<<5;
    int tx = threadIdx.x, ty = threadIdx.y;
#pragma unroll
    for (int i = ty; i < 32; i += 8)
        t[i][tx] = xp[(size_t)(r0+i)*ldx + c0 + tx];
    __syncthreads();
#pragma unroll
    for (int i = ty; i < 32; i += 8){
        float v = t[tx][i];
        size_t o = (size_t)(c0+i)*R + r0 + tx;
        __nv_bfloat16 h = __float2bfloat16(v);
        hp[o] = h;
        lp[o] = __float2bfloat16(v - __bfloat162float(h));
    }
}

// ---------------- elementwise / small kernels --------------------------------
// layernorm + relu, writing split bf16 (hi/lo) directly
__global__ void ln_relu_split_k(const float* __restrict__ h, const float* __restrict__ g,
                                const float* __restrict__ b,
                                __nv_bfloat16* __restrict__ oh, __nv_bfloat16* __restrict__ ol){
    __shared__ float red[2][8];
    int r = blockIdx.x;
    const float* row = h + (size_t)r*NH;
    int t = threadIdx.x;                   // 256 threads, 2 elems (NH=512)
    float v0 = row[t], v1 = row[t + 256];
    float s  = v0 + v1;
    float ss = v0*v0 + v1*v1;
#pragma unroll
    for (int o = 16; o; o >>= 1){
        s  += __shfl_xor_sync(0xffffffffu, s,  o);
        ss += __shfl_xor_sync(0xffffffffu, ss, o);
    }
    if ((t & 31) == 0){ red[0][t>>5] = s; red[1][t>>5] = ss; }
    __syncthreads();
    float tot = 0.f, tot2 = 0.f;
#pragma unroll
    for (int i = 0; i < 8; i++){ tot += red[0][i]; tot2 += red[1][i]; }
    float mu  = tot  * (1.0f/NH);
    float var = tot2 * (1.0f/NH) - mu*mu;
    float is  = rsqrtf(var + 1e-5f);
    float o0 = fmaxf(fmaf((v0-mu)*is, g[t],       b[t]),       0.0f);
    float o1 = fmaxf(fmaf((v1-mu)*is, g[t + 256], b[t + 256]), 0.0f);
    size_t base = (size_t)r*NH;
    __nv_bfloat16 h0 = __float2bfloat16(o0), h1 = __float2bfloat16(o1);
    oh[base + t]       = h0;
    ol[base + t]       = __float2bfloat16(o0 - __bfloat162float(h0));
    oh[base + t + 256] = h1;
    ol[base + t + 256] = __float2bfloat16(o1 - __bfloat162float(h1));
}
__global__ void dcoef_k(const float* __restrict__ tin, const float* __restrict__ w2,
                        const float* __restrict__ b2, float* __restrict__ dc){
    __shared__ float red[8];
    int r = blockIdx.x;
    int t = threadIdx.x;
    float s = tin[(size_t)r*NDF + t] * w2[t];
#pragma unroll
    for (int o = 16; o; o >>= 1) s += __shfl_xor_sync(0xffffffffu, s, o);
    if ((t & 31) == 0) red[t>>5] = s;
    __syncthreads();
    if (t == 0){
        float tot = 0.f;
#pragma unroll
        for (int i = 0; i < 8; i++) tot += red[i];
        dc[r] = 1.0f/(1.0f + expf(-(tot + b2[0])));
    }
}
// y-combine, fused with split of the result (A-side operand for next eval)
__global__ void combine_k(float* __restrict__ out, const float* __restrict__ y,
                          __nv_bfloat16* __restrict__ oh, __nv_bfloat16* __restrict__ ol,
                          float dt, int nk,
                          float c0, float c1, float c2, float c3, float c4, float c5){
    int idx = blockIdx.x*blockDim.x + threadIdx.x;
    if (idx >= ROWS*NF) return;
    float c[6] = {c0, c1, c2, c3, c4, c5};
    float v = y[idx];
    for (int i = 0; i < nk; i++) v = fmaf(dt*c[i], g_k[i][idx], v);
    out[idx] = v;
    __nv_bfloat16 h = __float2bfloat16(v);
    oh[idx] = h;
    ol[idx] = __float2bfloat16(v - __bfloat162float(h));
}

// ---------------- split-bf16 tensor-core GEMM (mma.sync m16n8k16) ------------
// D[m,n] = sum_k A[m,k]*B[n,k], A=Ah+Al, B=Bh+Bl (lo*lo dropped), fp32 accum.
// BM=128, BN=64, BK=32; 8 warps (4m x 2n), warp tile 32x32.
// mode 0: C = acc + bias[(m>>11)*bstride + n], optional relu.
// mode 1: rows offset z*NN, B offset z*Nt*K, C = dh - dc*acc.
#define MMA16816(d, a, b) \
    asm volatile("mma.sync.aligned.m16n8k16.row.col.f32.bf16.bf16.f32 " \
        "{%0,%1,%2,%3}, {%4,%5,%6,%7}, {%8,%9}, {%0,%1,%2,%3};" \
        : "+f"((d)[0]),"+f"((d)[1]),"+f"((d)[2]),"+f"((d)[3]) \
        : "r"((a)[0]),"r"((a)[1]),"r"((a)[2]),"r"((a)[3]), \
          "r"((b)[0]),"r"((b)[1]))

__global__ __launch_bounds__(256) void mmagemm_k(
    const __nv_bfloat16* __restrict__ Ah, const __nv_bfloat16* __restrict__ Al,
    const __nv_bfloat16* __restrict__ Bh, const __nv_bfloat16* __restrict__ Bl,
    const float* __restrict__ bias, int bstride, int relu,
    const float* __restrict__ dh, const float* __restrict__ dc,
    float* __restrict__ C, int Nt, int K, int mode)
{
    constexpr int LDS = 40;                      // padded row (bf16), bank-conflict-free
    extern __shared__ __nv_bfloat16 smem[];
    __nv_bfloat16* sAh = smem;                   // 2 x 128 x LDS
    __nv_bfloat16* sAl = sAh + 2*128*LDS;
    __nv_bfloat16* sBh = sAl + 2*128*LDS;        // 2 x 64 x LDS
    __nv_bfloat16* sBl = sBh + 2*64*LDS;

    const int tid  = threadIdx.x;
    const int wid  = tid >> 5, lane = tid & 31;
    const int wm   = wid >> 1, wn = wid & 1;     // 4x2 warp grid
    const int g    = lane >> 2, tig = lane & 3;
    const int m0   = blockIdx.y << 7;
    const int n0   = blockIdx.x << 6;

    if (mode == 1){
        size_t zo = (size_t)blockIdx.z * Nt * K;
        Bh += zo; Bl += zo;
    }

    const int arow = tid >> 1, acol = (tid & 1) << 4;   // 2 x uint4 per thread
    const int brow = tid >> 2, bcol = (tid & 3) << 3;   // 1 x uint4 per thread
    const __nv_bfloat16* pAh = Ah + (size_t)(m0 + arow)*K + acol;
    const __nv_bfloat16* pAl = Al + (size_t)(m0 + arow)*K + acol;
    const __nv_bfloat16* pBh = Bh + (size_t)(n0 + brow)*K + bcol;
    const __nv_bfloat16* pBl = Bl + (size_t)(n0 + brow)*K + bcol;

    float acc[2][4][4];
#pragma unroll
    for (int i = 0; i < 2; i++)
#pragma unroll
        for (int j = 0; j < 4; j++)
#pragma unroll
            for (int q = 0; q < 4; q++) acc[i][j][q] = 0.0f;

    // preload tile 0
    uint4 rah0 = *(const uint4*)(pAh);
    uint4 rah1 = *(const uint4*)(pAh + 8);
    uint4 ral0 = *(const uint4*)(pAl);
    uint4 ral1 = *(const uint4*)(pAl + 8);
    uint4 rbh  = *(const uint4*)(pBh);
    uint4 rbl  = *(const uint4*)(pBl);
    *(uint4*)&sAh[arow*LDS + acol]     = rah0;
    *(uint4*)&sAh[arow*LDS + acol + 8] = rah1;
    *(uint4*)&sAl[arow*LDS + acol]     = ral0;
    *(uint4*)&sAl[arow*LDS + acol + 8] = ral1;
    *(uint4*)&sBh[brow*LDS + bcol]     = rbh;
    *(uint4*)&sBl[brow*LDS + bcol]     = rbl;
    __syncthreads();

    const int nkt = K >> 5;
    for (int kt = 0; kt < nkt; kt++){
        const int cb = kt & 1;
        if (kt + 1 < nkt){
            const int k0 = (kt + 1) << 5;
            rah0 = *(const uint4*)(pAh + k0);
            rah1 = *(const uint4*)(pAh + k0 + 8);
            ral0 = *(const uint4*)(pAl + k0);
            ral1 = *(const uint4*)(pAl + k0 + 8);
            rbh  = *(const uint4*)(pBh + k0);
            rbl  = *(const uint4*)(pBl + k0);
        }
        const __nv_bfloat16* cAh = sAh + cb*128*LDS;
        const __nv_bfloat16* cAl = sAl + cb*128*LDS;
        const __nv_bfloat16* cBh = sBh + cb*64*LDS;
        const __nv_bfloat16* cBl = sBl + cb*64*LDS;
#pragma unroll
        for (int kk = 0; kk < 2; kk++){
            const int kb = kk*16 + tig*2;
            uint32_t afh[2][4], afl[2][4], bfh[4][2], bfl[4][2];
#pragma unroll
            for (int i = 0; i < 2; i++){
                const int r = wm*32 + i*16 + g;
                const __nv_bfloat16* p0 = cAh + r*LDS + kb;
                const __nv_bfloat16* p1 = cAh + (r+8)*LDS + kb;
                afh[i][0] = *(const uint32_t*)p0;
                afh[i][1] = *(const uint32_t*)p1;
                afh[i][2] = *(const uint32_t*)(p0 + 8);
                afh[i][3] = *(const uint32_t*)(p1 + 8);
                const __nv_bfloat16* q0 = cAl + r*LDS + kb;
                const __nv_bfloat16* q1 = cAl + (r+8)*LDS + kb;
                afl[i][0] = *(const uint32_t*)q0;
                afl[i][1] = *(const uint32_t*)q1;
                afl[i][2] = *(const uint32_t*)(q0 + 8);
                afl[i][3] = *(const uint32_t*)(q1 + 8);
            }
#pragma unroll
            for (int j = 0; j < 4; j++){
                const int r = wn*32 + j*8 + g;
                bfh[j][0] = *(const uint32_t*)(cBh + r*LDS + kb);
                bfh[j][1] = *(const uint32_t*)(cBh + r*LDS + kb + 8);
                bfl[j][0] = *(const uint32_t*)(cBl + r*LDS + kb);
                bfl[j][1] = *(const uint32_t*)(cBl + r*LDS + kb + 8);
            }
#pragma unroll
            for (int i = 0; i < 2; i++)
#pragma unroll
                for (int j = 0; j < 4; j++){
                    MMA16816(acc[i][j], afh[i], bfh[j]);
                    MMA16816(acc[i][j], afh[i], bfl[j]);
                    MMA16816(acc[i][j], afl[i], bfh[j]);
                }
        }
        if (kt + 1 < nkt){
            const int nb = (kt + 1) & 1;
            *(uint4*)&sAh[nb*128*LDS + arow*LDS + acol]     = rah0;
            *(uint4*)&sAh[nb*128*LDS + arow*LDS + acol + 8] = rah1;
            *(uint4*)&sAl[nb*128*LDS + arow*LDS + acol]     = ral0;
            *(uint4*)&sAl[nb*128*LDS + arow*LDS + acol + 8] = ral1;
            *(uint4*)&sBh[nb*64*LDS + brow*LDS + bcol]      = rbh;
            *(uint4*)&sBl[nb*64*LDS + brow*LDS + bcol]      = rbl;
            __syncthreads();
        }
    }

    // ---------------- epilogue ----------------
    if (mode == 0){
        const float* bp = bias + (size_t)(m0 >> 11)*bstride;
#pragma unroll
        for (int i = 0; i < 2; i++){
            const int ra = m0 + wm*32 + i*16 + g;
#pragma unroll
            for (int j = 0; j < 4; j++){
                const int col = n0 + wn*32 + j*8 + tig*2;
                const float b0 = bp[col], b1 = bp[col+1];
                float2 v0 = make_float2(acc[i][j][0] + b0, acc[i][j][1] + b1);
                float2 v1 = make_float2(acc[i][j][2] + b0, acc[i][j][3] + b1);
                if (relu){
                    v0.x = fmaxf(v0.x, 0.f); v0.y = fmaxf(v0.y, 0.f);
                    v1.x = fmaxf(v1.x, 0.f); v1.y = fmaxf(v1.y, 0.f);
                }
                *(float2*)&C[(size_t)ra*Nt + col]     = v0;
                *(float2*)&C[(size_t)(ra+8)*Nt + col] = v1;
            }
        }
    } else {
#pragma unroll
        for (int i = 0; i < 2; i++){
            const int ra = blockIdx.z*NN + m0 + wm*32 + i*16 + g;
            const float da = dc[ra], db = dc[ra + 8];
#pragma unroll
            for (int j = 0; j < 4; j++){
                const int col = n0 + wn*32 + j*8 + tig*2;
                const float* dpa = dh + (size_t)ra*Nt + col;
                const float* dpb = dh + (size_t)(ra+8)*Nt + col;
                float2 v0 = make_float2(dpa[0] - da*acc[i][j][0], dpa[1] - da*acc[i][j][1]);
                float2 v1 = make_float2(dpb[0] - db*acc[i][j][2], dpb[1] - db*acc[i][j][3]);
                *(float2*)&C[(size_t)ra*Nt + col]     = v0;
                *(float2*)&C[(size_t)(ra+8)*Nt + col] = v1;
            }
        }
    }
}

// ---------------- host --------------------------------------------------------
static void* sym_addr(const void* s){
    void* p = nullptr;
    cudaGetSymbolAddress(&p, s);
    return p;
}

extern "C" void kernel_launch(void* const* d_in, const int* in_sizes, int n_in,
                              void* d_out, int out_size)
{
    const float* state = (const float*)d_in[0];
    const float* ctx   = (const float*)d_in[1];
    const float* ea    = (const float*)d_in[2];
    const int*   ei    = (const int*)  d_in[3];
    const float* ew_w1 = (const float*)d_in[4];
    const float* ew_b1 = (const float*)d_in[5];
    const float* ew_w2 = (const float*)d_in[6];
    const float* ew_b2 = (const float*)d_in[7];
    const float* td_w1 = (const float*)d_in[8];
    const float* td_b1 = (const float*)d_in[9];
    const float* ln1_g = (const float*)d_in[10];
    const float* ln1_b = (const float*)d_in[11];
    const float* td_w2 = (const float*)d_in[12];
    const float* td_b2 = (const float*)d_in[13];
    const float* ln2_g = (const float*)d_in[14];
    const float* ln2_b = (const float*)d_in[15];
    const float* td_w3 = (const float*)d_in[16];
    const float* td_b3 = (const float*)d_in[17];
    const float* df_w1 = (const float*)d_in[18];
    const float* df_b1 = (const float*)d_in[19];
    const float* df_w2 = (const float*)d_in[20];
    const float* df_b2 = (const float*)d_in[21];

    float* L    = (float*)sym_addr(g_L);
    float* deg  = (float*)sym_addr(g_deg);
    float* ew   = (float*)sym_addr(g_ew);
    float* y    = (float*)sym_addr(g_y);
    float* yi   = (float*)sym_addr(g_yi);
    float* h1   = (float*)sym_addr(g_h1);
    float* h2   = (float*)sym_addr(g_h2);
    float* dh   = (float*)sym_addr(g_dh);
    float* tbuf = (float*)sym_addr(g_t);
    float* dc   = (float*)sym_addr(g_dc);
    float* cb   = (float*)sym_addr(g_cb);
    float* kbuf = (float*)sym_addr(g_k);
    __nv_bfloat16* Lbh = (__nv_bfloat16*)sym_addr(g_Lbh);
    __nv_bfloat16* Lbl = (__nv_bfloat16*)sym_addr(g_Lbl);
    __nv_bfloat16* w1h = (__nv_bfloat16*)sym_addr(g_w1h);
    __nv_bfloat16* w1l = (__nv_bfloat16*)sym_addr(g_w1l);
    __nv_bfloat16* w2h = (__nv_bfloat16*)sym_addr(g_w2h);
    __nv_bfloat16* w2l = (__nv_bfloat16*)sym_addr(g_w2l);
    __nv_bfloat16* w3h = (__nv_bfloat16*)sym_addr(g_w3h);
    __nv_bfloat16* w3l = (__nv_bfloat16*)sym_addr(g_w3l);
    __nv_bfloat16* dwh = (__nv_bfloat16*)sym_addr(g_dwh);
    __nv_bfloat16* dwl = (__nv_bfloat16*)sym_addr(g_dwl);
    __nv_bfloat16* yh  = (__nv_bfloat16*)sym_addr(g_yh);
    __nv_bfloat16* yl  = (__nv_bfloat16*)sym_addr(g_yl);
    __nv_bfloat16* yth = (__nv_bfloat16*)sym_addr(g_yth);
    __nv_bfloat16* ytl = (__nv_bfloat16*)sym_addr(g_ytl);
    __nv_bfloat16* ah  = (__nv_bfloat16*)sym_addr(g_ah);
    __nv_bfloat16* al  = (__nv_bfloat16*)sym_addr(g_al);

    const int SMEM = (2*128*40 + 2*128*40 + 2*64*40 + 2*64*40) * 2;  // 61440 B
    cudaFuncSetAttribute(mmagemm_k, cudaFuncAttributeMaxDynamicSharedMemorySize, SMEM);

    // ---- Laplacian + operand prep (once per launch) ----
    deg_init_k<<<(NN + 255)/256, 256>>>(deg);
    edge_k<<<NE/256, 256>>>(ea, ei, ew_w1, ew_b1, ew_w2, ew_b2, ew, deg);
    initL_k<<<(NN*NN)/256, 256>>>(L, deg);
    scatter_k<<<NE/256, 256>>>(L, deg, ew, ei);
    split_k<<<(NN*NN)/256, 256>>>(L, Lbh, Lbl, NN*NN);
    // weight transposes: out[n][k] = w[k][n]
    tsplit_k<<<dim3(NH/32, NF/32, 1),  dim3(32,8)>>>(td_w1, NH, 0, 0, NF,  w1h, w1l);
    tsplit_k<<<dim3(NH/32, NH/32, 1),  dim3(32,8)>>>(td_w2, NH, 0, 0, NH,  w2h, w2l);
    tsplit_k<<<dim3(NF/32, NH/32, 1),  dim3(32,8)>>>(td_w3, NF, 0, 0, NH,  w3h, w3l);
    tsplit_k<<<dim3(NDF/32, NF/32, 1), dim3(32,8)>>>(df_w1, NDF, 0, 0, NF, dwh, dwl);
    ctxbias_k<<<dim3(NH/128, NB), 128>>>(ctx, td_w1, td_b1, cb);

    cudaMemcpyAsync(y, state, sizeof(float)*ROWS*NF, cudaMemcpyDeviceToDevice, 0);
    split_k<<<(ROWS*NF)/256, 256>>>(y, yh, yl, ROWS*NF);

    // invariant: g_yh/g_yl always hold split(yin) when eval_f runs
    auto eval_f = [&](const float* yin, int ki){
        tsplit_k<<<dim3(NF/32, NN/32, NB), dim3(32,8)>>>(yin, NF,
                (size_t)NN*NF, (size_t)NF*NN, NN, yth, ytl);
        // layer1: yin @ W1_state + cb[batch]   (ctx half folded into cb)
        mmagemm_k<<<dim3(NH/64, ROWS/128), 256, SMEM>>>(
            yh, yl, w1h, w1l, cb, NH, 0, nullptr, nullptr, h1, NH, NF, 0);
        ln_relu_split_k<<<ROWS, 256>>>(h1, ln1_g, ln1_b, ah, al);
        mmagemm_k<<<dim3(NH/64, ROWS/128), 256, SMEM>>>(
            ah, al, w2h, w2l, td_b2, 0, 0, nullptr, nullptr, h2, NH, NH, 0);
        ln_relu_split_k<<<ROWS, 256>>>(h2, ln2_g, ln2_b, ah, al);
        mmagemm_k<<<dim3(NF/64, ROWS/128), 256, SMEM>>>(
            ah, al, w3h, w3l, td_b3, 0, 0, nullptr, nullptr, dh, NF, NH, 0);
        mmagemm_k<<<dim3(NDF/64, ROWS/128), 256, SMEM>>>(
            yh, yl, dwh, dwl, df_b1, 0, 1, nullptr, nullptr, tbuf, NDF, NF, 0);
        dcoef_k<<<ROWS, 256>>>(tbuf, df_w2, df_b2, dc);
        // k = dh - dcoef * (L @ y)
        mmagemm_k<<<dim3(NF/64, NN/128, NB), 256, SMEM>>>(
            Lbh, Lbl, yth, ytl, nullptr, 0, 0, dh, dc,
            kbuf + (size_t)ki*ROWS*NF, NF, NN, 1);
    };

    const float dt = 0.25f;   // (T1-T0)/N_STEPS
    const int nblk = (ROWS*NF)/256;
    for (int s = 0; s < 4; s++){
        // k7 of dopri5 is dead (b7 == 0, no FSAL reuse) -> 6 stages only
        eval_f(y, 0);
        combine_k<<<nblk, 256>>>(yi, y, yh, yl, dt, 1,
            (float)(1.0/5.0), 0.f, 0.f, 0.f, 0.f, 0.f);
        eval_f(yi, 1);
        combine_k<<<nblk, 256>>>(yi, y, yh, yl, dt, 2,
            (float)(3.0/40.0), (float)(9.0/40.0), 0.f, 0.f, 0.f, 0.f);
        eval_f(yi, 2);
        combine_k<<<nblk, 256>>>(yi, y, yh, yl, dt, 3,
            (float)(44.0/45.0), (float)(-56.0/15.0), (float)(32.0/9.0), 0.f, 0.f, 0.f);
        eval_f(yi, 3);
        combine_k<<<nblk, 256>>>(yi, y, yh, yl, dt, 4,
            (float)(19372.0/6561.0), (float)(-25360.0/2187.0),
            (float)(64448.0/6561.0), (float)(-212.0/729.0), 0.f, 0.f);
        eval_f(yi, 4);
        combine_k<<<nblk, 256>>>(yi, y, yh, yl, dt, 5,
            (float)(9017.0/3168.0), (float)(-355.0/33.0),
            (float)(46732.0/5247.0), (float)(49.0/176.0),
            (float)(-5103.0/18656.0), 0.f);
        eval_f(yi, 5);
        combine_k<<<nblk, 256>>>(y, y, yh, yl, dt, 6,
            (float)(35.0/384.0), 0.f, (float)(500.0/1113.0),
            (float)(125.0/192.0), (float)(-2187.0/6784.0), (float)(11.0/84.0));
    }

    cudaMemcpyAsync(d_out, y, sizeof(float)*ROWS*NF, cudaMemcpyDeviceToDevice, 0);
}

// round 8
// speedup vs baseline: 2.5464x; 1.2775x over previous
#include <cuda_runtime.h>
#include <cuda_bf16.h>
#include <math.h>
#include <stdint.h>

#define NB 4
#define NN 2048
#define NF 256
#define NH 512
#define NDF 256          /* H/2 */
#define NE 65536
#define ROWS (NB*NN)     /* 8192 */

// ---------------- fp32 scratch ----------------------------------------------
__device__ float g_L[NN*NN];
__device__ float g_deg[NN];
__device__ float g_ew[NE];
__device__ float g_y [ROWS*NF];
__device__ float g_yi[ROWS*NF];
__device__ float g_h1[ROWS*NH];
__device__ float g_h2[ROWS*NH];
__device__ float g_dh[ROWS*NF];
__device__ float g_t [ROWS*NDF];
__device__ float g_dc[ROWS];
__device__ float g_cb[NB*NH];
__device__ float g_k [6][ROWS*NF];
// ---------------- bf16 split operands (all B-side kept in natural [K][N]) ----
__device__ __nv_bfloat16 g_Lbh[NN*NN],  g_Lbl[NN*NN];      // L (A side) [M,K]
__device__ __nv_bfloat16 g_w1h[NF*NH],  g_w1l[NF*NH];      // W1_state [K=F][N=H]
__device__ __nv_bfloat16 g_w2h[NH*NH],  g_w2l[NH*NH];      // W2 [H][H]
__device__ __nv_bfloat16 g_w3h[NH*NF],  g_w3l[NH*NF];      // W3 [H][F]
__device__ __nv_bfloat16 g_dwh[NF*NDF], g_dwl[NF*NDF];     // df_w1 [F][H/2]
__device__ __nv_bfloat16 g_yh[ROWS*NF], g_yl[ROWS*NF];     // yin (A side AND B side of LH)
__device__ __nv_bfloat16 g_ah[ROWS*NH], g_al[ROWS*NH];     // h1/h2 split (A side)

// ---------------- Laplacian build --------------------------------------------
__global__ void deg_init_k(float* deg){
    int i = blockIdx.x*blockDim.x + threadIdx.x;
    if (i < NN) deg[i] = 1.0f;
}
__global__ void edge_k(const float* __restrict__ ea, const int* __restrict__ ei,
                       const float* __restrict__ w1, const float* __restrict__ b1,
                       const float* __restrict__ w2, const float* __restrict__ b2,
                       float* __restrict__ ew, float* __restrict__ deg){
    int e = blockIdx.x*blockDim.x + threadIdx.x;
    if (e >= NE) return;
    float a = ea[e];
    float s = b2[0];
#pragma unroll
    for (int j = 0; j < 32; j++){
        float h = fmaxf(fmaf(a, w1[j], b1[j]), 0.0f);
        s = fmaf(h, w2[j], s);
    }
    ew[e] = 1.0f/(1.0f + expf(-s));
    atomicAdd(&deg[ei[NE + e]], 1.0f);
}
__global__ void initL_k(float* __restrict__ L, const float* __restrict__ deg){
    int idx = blockIdx.x*blockDim.x + threadIdx.x;
    int i = idx >> 11, j = idx & (NN-1);
    float v = 0.0f;
    if (i == j){
        float dis = rsqrtf(deg[i]);
        v = 1.0f - dis*dis;
    }
    L[idx] = v;
}
__global__ void scatter_k(float* __restrict__ L, const float* __restrict__ deg,
                          const float* __restrict__ ew, const int* __restrict__ ei){
    int e = blockIdx.x*blockDim.x + threadIdx.x;
    if (e >= NE) return;
    int r = ei[e], c = ei[NE + e];
    float w = rsqrtf(deg[r]) * ew[e] * rsqrtf(deg[c]);
    atomicAdd(&L[r*NN + c], -w);
}
__global__ void ctxbias_k(const float* __restrict__ ctx, const float* __restrict__ w1,
                          const float* __restrict__ b1, float* __restrict__ cb){
    int h = blockIdx.x*blockDim.x + threadIdx.x;
    int b = blockIdx.y;
    float s = b1[h];
#pragma unroll 4
    for (int f = 0; f < NF; f++)
        s = fmaf(ctx[b*NF + f], w1[(size_t)(NF + f)*NH + h], s);
    cb[b*NH + h] = s;
}

// ---------------- split -------------------------------------------------------
__global__ void split_k(const float* __restrict__ x, __nv_bfloat16* __restrict__ hi,
                        __nv_bfloat16* __restrict__ lo, int n){
    int i = blockIdx.x*blockDim.x + threadIdx.x;
    if (i >= n) return;
    float v = x[i];
    __nv_bfloat16 h = __float2bfloat16(v);
    hi[i] = h;
    lo[i] = __float2bfloat16(v - __bfloat162float(h));
}

// ---------------- elementwise / small kernels --------------------------------
__global__ void ln_relu_split_k(const float* __restrict__ h, const float* __restrict__ g,
                                const float* __restrict__ b,
                                __nv_bfloat16* __restrict__ oh, __nv_bfloat16* __restrict__ ol){
    __shared__ float red[2][8];
    int r = blockIdx.x;
    const float* row = h + (size_t)r*NH;
    int t = threadIdx.x;                   // 256 threads, 2 elems (NH=512)
    float v0 = row[t], v1 = row[t + 256];
    float s  = v0 + v1;
    float ss = v0*v0 + v1*v1;
#pragma unroll
    for (int o = 16; o; o >>= 1){
        s  += __shfl_xor_sync(0xffffffffu, s,  o);
        ss += __shfl_xor_sync(0xffffffffu, ss, o);
    }
    if ((t & 31) == 0){ red[0][t>>5] = s; red[1][t>>5] = ss; }
    __syncthreads();
    float tot = 0.f, tot2 = 0.f;
#pragma unroll
    for (int i = 0; i < 8; i++){ tot += red[0][i]; tot2 += red[1][i]; }
    float mu  = tot  * (1.0f/NH);
    float var = tot2 * (1.0f/NH) - mu*mu;
    float is  = rsqrtf(var + 1e-5f);
    float o0 = fmaxf(fmaf((v0-mu)*is, g[t],       b[t]),       0.0f);
    float o1 = fmaxf(fmaf((v1-mu)*is, g[t + 256], b[t + 256]), 0.0f);
    size_t base = (size_t)r*NH;
    __nv_bfloat16 h0 = __float2bfloat16(o0), h1 = __float2bfloat16(o1);
    oh[base + t]       = h0;
    ol[base + t]       = __float2bfloat16(o0 - __bfloat162float(h0));
    oh[base + t + 256] = h1;
    ol[base + t + 256] = __float2bfloat16(o1 - __bfloat162float(h1));
}
__global__ void dcoef_k(const float* __restrict__ tin, const float* __restrict__ w2,
                        const float* __restrict__ b2, float* __restrict__ dc){
    __shared__ float red[8];
    int r = blockIdx.x;
    int t = threadIdx.x;
    float s = tin[(size_t)r*NDF + t] * w2[t];
#pragma unroll
    for (int o = 16; o; o >>= 1) s += __shfl_xor_sync(0xffffffffu, s, o);
    if ((t & 31) == 0) red[t>>5] = s;
    __syncthreads();
    if (t == 0){
        float tot = 0.f;
#pragma unroll
        for (int i = 0; i < 8; i++) tot += red[i];
        dc[r] = 1.0f/(1.0f + expf(-(tot + b2[0])));
    }
}
__global__ void combine_k(float* __restrict__ out, const float* __restrict__ y,
                          __nv_bfloat16* __restrict__ oh, __nv_bfloat16* __restrict__ ol,
                          float dt, int nk,
                          float c0, float c1, float c2, float c3, float c4, float c5){
    int idx = blockIdx.x*blockDim.x + threadIdx.x;
    if (idx >= ROWS*NF) return;
    float c[6] = {c0, c1, c2, c3, c4, c5};
    float v = y[idx];
    for (int i = 0; i < nk; i++) v = fmaf(dt*c[i], g_k[i][idx], v);
    out[idx] = v;
    __nv_bfloat16 h = __float2bfloat16(v);
    oh[idx] = h;
    ol[idx] = __float2bfloat16(v - __bfloat162float(h));
}

// ---------------- split-bf16 tensor-core GEMM (mma.sync + ldmatrix) ----------
// D[m,n] = sum_k A[m,k]*B[k,n], A=Ah+Al, B=Bh+Bl (lo*lo dropped), fp32 accum.
// A: [M,K] row-major. B: [K,N] row-major (natural layout; b-frags via ldmatrix.trans).
// BM=128, BN=64, BK=32; 8 warps (4m x 2n), warp tile 32x32.
// mode 0: C = acc + bias[(m>>11)*bstride + n], optional relu.
// mode 1: rows offset z*NN, B offset z*K*ldb, C = dh - dc*acc.
__device__ __forceinline__ uint32_t smem_u32(const void* p){
    uint32_t a;
    asm("{ .reg .u64 t; cvta.to.shared.u64 t, %1; cvt.u32.u64 %0, t; }" : "=r"(a) : "l"(p));
    return a;
}
#define MMA16816(d, a, b) \
    asm volatile("mma.sync.aligned.m16n8k16.row.col.f32.bf16.bf16.f32 " \
        "{%0,%1,%2,%3}, {%4,%5,%6,%7}, {%8,%9}, {%0,%1,%2,%3};" \
        : "+f"((d)[0]),"+f"((d)[1]),"+f"((d)[2]),"+f"((d)[3]) \
        : "r"((a)[0]),"r"((a)[1]),"r"((a)[2]),"r"((a)[3]), \
          "r"((b)[0]),"r"((b)[1]))
#define LDSM4(r0,r1,r2,r3,a) \
    asm volatile("ldmatrix.sync.aligned.m8n8.x4.shared.b16 {%0,%1,%2,%3}, [%4];" \
        : "=r"(r0),"=r"(r1),"=r"(r2),"=r"(r3) : "r"(a))
#define LDSM4T(r0,r1,r2,r3,a) \
    asm volatile("ldmatrix.sync.aligned.m8n8.x4.trans.shared.b16 {%0,%1,%2,%3}, [%4];" \
        : "=r"(r0),"=r"(r1),"=r"(r2),"=r"(r3) : "r"(a))

__global__ __launch_bounds__(256) void mmagemm_k(
    const __nv_bfloat16* __restrict__ Ah, const __nv_bfloat16* __restrict__ Al,
    const __nv_bfloat16* __restrict__ Bh, const __nv_bfloat16* __restrict__ Bl,
    int ldb,
    const float* __restrict__ bias, int bstride, int relu,
    const float* __restrict__ dh, const float* __restrict__ dc,
    float* __restrict__ C, int Nt, int K, int mode)
{
    constexpr int LDSA = 40;   // 80B rows: LDSM phases conflict-free
    constexpr int LDSB = 72;   // 144B rows: LDSM.T phases conflict-free
    extern __shared__ __nv_bfloat16 smem[];
    __nv_bfloat16* sAh = smem;                    // 2 x 128 x LDSA
    __nv_bfloat16* sAl = sAh + 2*128*LDSA;
    __nv_bfloat16* sBh = sAl + 2*128*LDSA;        // 2 x 32 x LDSB
    __nv_bfloat16* sBl = sBh + 2*32*LDSB;

    const int tid  = threadIdx.x;
    const int wid  = tid >> 5, lane = tid & 31;
    const int wm   = wid >> 1, wn = wid & 1;     // 4x2 warp grid
    const int g    = lane >> 2, tig = lane & 3;
    const int m0   = blockIdx.y << 7;
    const int n0   = blockIdx.x << 6;

    if (mode == 1){
        size_t zo = (size_t)blockIdx.z * K * ldb;
        Bh += zo; Bl += zo;
    }

    // ldmatrix per-lane addresses
    const uint32_t uAh = smem_u32(sAh), uAl = smem_u32(sAl);
    const uint32_t uBh = smem_u32(sBh), uBl = smem_u32(sBl);
    const int l7 = lane & 7, l8 = (lane >> 3) & 1, l16 = lane >> 4;
    // A frag (16x16): matrices (r0-7,k0-7)(r8-15,k0-7)(r0-7,k8-15)(r8-15,k8-15)
    const uint32_t aoff0 = (uint32_t)((wm*32 + l7 + l8*8)*LDSA + l16*8)*2;
    const uint32_t aoff1 = aoff0 + 16*LDSA*2;
    // B frag (k16 x n16, trans): matrices (k0-7,n0-7)(k8-15,n0-7)(k0-7,n8-15)(k8-15,n8-15)
    const uint32_t boff0 = (uint32_t)((l7 + l8*8)*LDSB + wn*32 + l16*8)*2;
    const uint32_t boff1 = boff0 + 16*2;

    // global staging
    const int arow = tid >> 1, acol = (tid & 1) << 4;   // 2 x uint4 per thread
    const int brow = tid >> 3, bcol = (tid & 7) << 3;   // 1 x uint4 per thread
    const __nv_bfloat16* pAh = Ah + (size_t)(m0 + arow)*K + acol;
    const __nv_bfloat16* pAl = Al + (size_t)(m0 + arow)*K + acol;
    const __nv_bfloat16* pBh = Bh + (size_t)brow*ldb + n0 + bcol;
    const __nv_bfloat16* pBl = Bl + (size_t)brow*ldb + n0 + bcol;

    float acc[2][4][4];
#pragma unroll
    for (int i = 0; i < 2; i++)
#pragma unroll
        for (int j = 0; j < 4; j++)
#pragma unroll
            for (int q = 0; q < 4; q++) acc[i][j][q] = 0.0f;

    // preload tile 0
    uint4 rah0 = *(const uint4*)(pAh);
    uint4 rah1 = *(const uint4*)(pAh + 8);
    uint4 ral0 = *(const uint4*)(pAl);
    uint4 ral1 = *(const uint4*)(pAl + 8);
    uint4 rbh  = *(const uint4*)(pBh);
    uint4 rbl  = *(const uint4*)(pBl);
    *(uint4*)&sAh[arow*LDSA + acol]     = rah0;
    *(uint4*)&sAh[arow*LDSA + acol + 8] = rah1;
    *(uint4*)&sAl[arow*LDSA + acol]     = ral0;
    *(uint4*)&sAl[arow*LDSA + acol + 8] = ral1;
    *(uint4*)&sBh[brow*LDSB + bcol]     = rbh;
    *(uint4*)&sBl[brow*LDSB + bcol]     = rbl;
    __syncthreads();

    const int nkt = K >> 5;
    for (int kt = 0; kt < nkt; kt++){
        const int cb = kt & 1;
        if (kt + 1 < nkt){
            const int k0 = (kt + 1) << 5;
            rah0 = *(const uint4*)(pAh + k0);
            rah1 = *(const uint4*)(pAh + k0 + 8);
            ral0 = *(const uint4*)(pAl + k0);
            ral1 = *(const uint4*)(pAl + k0 + 8);
            rbh  = *(const uint4*)(pBh + (size_t)k0*ldb);
            rbl  = *(const uint4*)(pBl + (size_t)k0*ldb);
        }
        const uint32_t oa = cb ? (uint32_t)(128*LDSA*2) : 0u;
        const uint32_t ob = cb ? (uint32_t)(32*LDSB*2)  : 0u;
#pragma unroll
        for (int kk = 0; kk < 2; kk++){
            const uint32_t ka = oa + (uint32_t)kk*16*2;
            const uint32_t kb = ob + (uint32_t)kk*16*LDSB*2;
            uint32_t afh[2][4], afl[2][4], bfh[4][2], bfl[4][2];
            LDSM4 (afh[0][0],afh[0][1],afh[0][2],afh[0][3], uAh + aoff0 + ka);
            LDSM4 (afh[1][0],afh[1][1],afh[1][2],afh[1][3], uAh + aoff1 + ka);
            LDSM4 (afl[0][0],afl[0][1],afl[0][2],afl[0][3], uAl + aoff0 + ka);
            LDSM4 (afl[1][0],afl[1][1],afl[1][2],afl[1][3], uAl + aoff1 + ka);
            LDSM4T(bfh[0][0],bfh[0][1],bfh[1][0],bfh[1][1], uBh + boff0 + kb);
            LDSM4T(bfh[2][0],bfh[2][1],bfh[3][0],bfh[3][1], uBh + boff1 + kb);
            LDSM4T(bfl[0][0],bfl[0][1],bfl[1][0],bfl[1][1], uBl + boff0 + kb);
            LDSM4T(bfl[2][0],bfl[2][1],bfl[3][0],bfl[3][1], uBl + boff1 + kb);
#pragma unroll
            for (int i = 0; i < 2; i++)
#pragma unroll
                for (int j = 0; j < 4; j++){
                    MMA16816(acc[i][j], afh[i], bfh[j]);
                    MMA16816(acc[i][j], afh[i], bfl[j]);
                    MMA16816(acc[i][j], afl[i], bfh[j]);
                }
        }
        if (kt + 1 < nkt){
            const int nb = (kt + 1) & 1;
            *(uint4*)&sAh[nb*128*LDSA + arow*LDSA + acol]     = rah0;
            *(uint4*)&sAh[nb*128*LDSA + arow*LDSA + acol + 8] = rah1;
            *(uint4*)&sAl[nb*128*LDSA + arow*LDSA + acol]     = ral0;
            *(uint4*)&sAl[nb*128*LDSA + arow*LDSA + acol + 8] = ral1;
            *(uint4*)&sBh[nb*32*LDSB + brow*LDSB + bcol]      = rbh;
            *(uint4*)&sBl[nb*32*LDSB + brow*LDSB + bcol]      = rbl;
            __syncthreads();
        }
    }

    // ---------------- epilogue ----------------
    if (mode == 0){
        const float* bp = bias + (size_t)(m0 >> 11)*bstride;
#pragma unroll
        for (int i = 0; i < 2; i++){
            const int ra = m0 + wm*32 + i*16 + g;
#pragma unroll
            for (int j = 0; j < 4; j++){
                const int col = n0 + wn*32 + j*8 + tig*2;
                const float b0 = bp[col], b1 = bp[col+1];
                float2 v0 = make_float2(acc[i][j][0] + b0, acc[i][j][1] + b1);
                float2 v1 = make_float2(acc[i][j][2] + b0, acc[i][j][3] + b1);
                if (relu){
                    v0.x = fmaxf(v0.x, 0.f); v0.y = fmaxf(v0.y, 0.f);
                    v1.x = fmaxf(v1.x, 0.f); v1.y = fmaxf(v1.y, 0.f);
                }
                *(float2*)&C[(size_t)ra*Nt + col]     = v0;
                *(float2*)&C[(size_t)(ra+8)*Nt + col] = v1;
            }
        }
    } else {
#pragma unroll
        for (int i = 0; i < 2; i++){
            const int ra = blockIdx.z*NN + m0 + wm*32 + i*16 + g;
            const float da = dc[ra], db = dc[ra + 8];
#pragma unroll
            for (int j = 0; j < 4; j++){
                const int col = n0 + wn*32 + j*8 + tig*2;
                const float* dpa = dh + (size_t)ra*Nt + col;
                const float* dpb = dh + (size_t)(ra+8)*Nt + col;
                float2 v0 = make_float2(dpa[0] - da*acc[i][j][0], dpa[1] - da*acc[i][j][1]);
                float2 v1 = make_float2(dpb[0] - db*acc[i][j][2], dpb[1] - db*acc[i][j][3]);
                *(float2*)&C[(size_t)ra*Nt + col]     = v0;
                *(float2*)&C[(size_t)(ra+8)*Nt + col] = v1;
            }
        }
    }
}

// ---------------- host --------------------------------------------------------
static void* sym_addr(const void* s){
    void* p = nullptr;
    cudaGetSymbolAddress(&p, s);
    return p;
}

extern "C" void kernel_launch(void* const* d_in, const int* in_sizes, int n_in,
                              void* d_out, int out_size)
{
    const float* state = (const float*)d_in[0];
    const float* ctx   = (const float*)d_in[1];
    const float* ea    = (const float*)d_in[2];
    const int*   ei    = (const int*)  d_in[3];
    const float* ew_w1 = (const float*)d_in[4];
    const float* ew_b1 = (const float*)d_in[5];
    const float* ew_w2 = (const float*)d_in[6];
    const float* ew_b2 = (const float*)d_in[7];
    const float* td_w1 = (const float*)d_in[8];
    const float* td_b1 = (const float*)d_in[9];
    const float* ln1_g = (const float*)d_in[10];
    const float* ln1_b = (const float*)d_in[11];
    const float* td_w2 = (const float*)d_in[12];
    const float* td_b2 = (const float*)d_in[13];
    const float* ln2_g = (const float*)d_in[14];
    const float* ln2_b = (const float*)d_in[15];
    const float* td_w3 = (const float*)d_in[16];
    const float* td_b3 = (const float*)d_in[17];
    const float* df_w1 = (const float*)d_in[18];
    const float* df_b1 = (const float*)d_in[19];
    const float* df_w2 = (const float*)d_in[20];
    const float* df_b2 = (const float*)d_in[21];

    float* L    = (float*)sym_addr(g_L);
    float* deg  = (float*)sym_addr(g_deg);
    float* ew   = (float*)sym_addr(g_ew);
    float* y    = (float*)sym_addr(g_y);
    float* yi   = (float*)sym_addr(g_yi);
    float* h1   = (float*)sym_addr(g_h1);
    float* h2   = (float*)sym_addr(g_h2);
    float* dh   = (float*)sym_addr(g_dh);
    float* tbuf = (float*)sym_addr(g_t);
    float* dc   = (float*)sym_addr(g_dc);
    float* cb   = (float*)sym_addr(g_cb);
    float* kbuf = (float*)sym_addr(g_k);
    __nv_bfloat16* Lbh = (__nv_bfloat16*)sym_addr(g_Lbh);
    __nv_bfloat16* Lbl = (__nv_bfloat16*)sym_addr(g_Lbl);
    __nv_bfloat16* w1h = (__nv_bfloat16*)sym_addr(g_w1h);
    __nv_bfloat16* w1l = (__nv_bfloat16*)sym_addr(g_w1l);
    __nv_bfloat16* w2h = (__nv_bfloat16*)sym_addr(g_w2h);
    __nv_bfloat16* w2l = (__nv_bfloat16*)sym_addr(g_w2l);
    __nv_bfloat16* w3h = (__nv_bfloat16*)sym_addr(g_w3h);
    __nv_bfloat16* w3l = (__nv_bfloat16*)sym_addr(g_w3l);
    __nv_bfloat16* dwh = (__nv_bfloat16*)sym_addr(g_dwh);
    __nv_bfloat16* dwl = (__nv_bfloat16*)sym_addr(g_dwl);
    __nv_bfloat16* yh  = (__nv_bfloat16*)sym_addr(g_yh);
    __nv_bfloat16* yl  = (__nv_bfloat16*)sym_addr(g_yl);
    __nv_bfloat16* ah  = (__nv_bfloat16*)sym_addr(g_ah);
    __nv_bfloat16* al  = (__nv_bfloat16*)sym_addr(g_al);

    // smem: A 2*2*128*40 + B 2*2*32*72 elems = 29696 * 2B
    const int SMEM = (2*2*128*40 + 2*2*32*72) * 2;   // 59392 B
    cudaFuncSetAttribute(mmagemm_k, cudaFuncAttributeMaxDynamicSharedMemorySize, SMEM);

    // ---- Laplacian + operand prep (once per launch) ----
    deg_init_k<<<(NN + 255)/256, 256>>>(deg);
    edge_k<<<NE/256, 256>>>(ea, ei, ew_w1, ew_b1, ew_w2, ew_b2, ew, deg);
    initL_k<<<(NN*NN)/256, 256>>>(L, deg);
    scatter_k<<<NE/256, 256>>>(L, deg, ew, ei);
    split_k<<<(NN*NN)/256, 256>>>(L, Lbh, Lbl, NN*NN);
    // weights kept in natural [K][N] layout (b-frags use ldmatrix.trans)
    split_k<<<(NF*NH)/256, 256>>>(td_w1, w1h, w1l, NF*NH);   // state rows only (first NF)
    split_k<<<(NH*NH)/256, 256>>>(td_w2, w2h, w2l, NH*NH);
    split_k<<<(NH*NF)/256, 256>>>(td_w3, w3h, w3l, NH*NF);
    split_k<<<(NF*NDF)/256, 256>>>(df_w1, dwh, dwl, NF*NDF);
    ctxbias_k<<<dim3(NH/128, NB), 128>>>(ctx, td_w1, td_b1, cb);

    cudaMemcpyAsync(y, state, sizeof(float)*ROWS*NF, cudaMemcpyDeviceToDevice, 0);
    split_k<<<(ROWS*NF)/256, 256>>>(y, yh, yl, ROWS*NF);

    // invariant: g_yh/g_yl always hold split(yin) when eval_f runs
    auto eval_f = [&](int ki){
        // layer1: yin @ W1_state + cb[batch]   (ctx half folded into cb)
        mmagemm_k<<<dim3(NH/64, ROWS/128), 256, SMEM>>>(
            yh, yl, w1h, w1l, NH, cb, NH, 0, nullptr, nullptr, h1, NH, NF, 0);
        ln_relu_split_k<<<ROWS, 256>>>(h1, ln1_g, ln1_b, ah, al);
        mmagemm_k<<<dim3(NH/64, ROWS/128), 256, SMEM>>>(
            ah, al, w2h, w2l, NH, td_b2, 0, 0, nullptr, nullptr, h2, NH, NH, 0);
        ln_relu_split_k<<<ROWS, 256>>>(h2, ln2_g, ln2_b, ah, al);
        mmagemm_k<<<dim3(NF/64, ROWS/128), 256, SMEM>>>(
            ah, al, w3h, w3l, NF, td_b3, 0, 0, nullptr, nullptr, dh, NF, NH, 0);
        mmagemm_k<<<dim3(NDF/64, ROWS/128), 256, SMEM>>>(
            yh, yl, dwh, dwl, NDF, df_b1, 0, 1, nullptr, nullptr, tbuf, NDF, NF, 0);
        dcoef_k<<<ROWS, 256>>>(tbuf, df_w2, df_b2, dc);
        // k = dh - dcoef * (L @ y)  — B = yin (row-major [node][feat]), no transpose needed
        mmagemm_k<<<dim3(NF/64, NN/128, NB), 256, SMEM>>>(
            Lbh, Lbl, yh, yl, NF, nullptr, 0, 0, dh, dc,
            kbuf + (size_t)ki*ROWS*NF, NF, NN, 1);
    };

    const float dt = 0.25f;   // (T1-T0)/N_STEPS
    const int nblk = (ROWS*NF)/256;
    for (int s = 0; s < 4; s++){
        // k7 of dopri5 is dead (b7 == 0, no FSAL reuse) -> 6 stages only
        eval_f(0);
        combine_k<<<nblk, 256>>>(yi, y, yh, yl, dt, 1,
            (float)(1.0/5.0), 0.f, 0.f, 0.f, 0.f, 0.f);
        eval_f(1);
        combine_k<<<nblk, 256>>>(yi, y, yh, yl, dt, 2,
            (float)(3.0/40.0), (float)(9.0/40.0), 0.f, 0.f, 0.f, 0.f);
        eval_f(2);
        combine_k<<<nblk, 256>>>(yi, y, yh, yl, dt, 3,
            (float)(44.0/45.0), (float)(-56.0/15.0), (float)(32.0/9.0), 0.f, 0.f, 0.f);
        eval_f(3);
        combine_k<<<nblk, 256>>>(yi, y, yh, yl, dt, 4,
            (float)(19372.0/6561.0), (float)(-25360.0/2187.0),
            (float)(64448.0/6561.0), (float)(-212.0/729.0), 0.f, 0.f);
        eval_f(4);
        combine_k<<<nblk, 256>>>(yi, y, yh, yl, dt, 5,
            (float)(9017.0/3168.0), (float)(-355.0/33.0),
            (float)(46732.0/5247.0), (float)(49.0/176.0),
            (float)(-5103.0/18656.0), 0.f);
        eval_f(5);
        combine_k<<<nblk, 256>>>(y, y, yh, yl, dt, 6,
            (float)(35.0/384.0), 0.f, (float)(500.0/1113.0),
            (float)(125.0/192.0), (float)(-2187.0/6784.0), (float)(11.0/84.0));
    }

    cudaMemcpyAsync(d_out, y, sizeof(float)*ROWS*NF, cudaMemcpyDeviceToDevice, 0);
}

// round 9
// speedup vs baseline: 3.4247x; 1.3449x over previous
#include <cuda_runtime.h>
#include <cuda_bf16.h>
#include <math.h>
#include <stdint.h>

#define NB 4
#define NN 2048
#define NF 256
#define NH 512
#define NDF 256          /* H/2 */
#define NE 65536
#define ROWS (NB*NN)     /* 8192 */
#define NCAT (NH + NDF)  /* 768: merged layer1 + dcoef GEMM width */

// ---------------- fp32 scratch ----------------------------------------------
__device__ float g_deg[NN];
__device__ float g_ew[NE];
__device__ float g_y [ROWS*NF];
__device__ float g_yi[ROWS*NF];
__device__ float g_h1e[ROWS*NCAT];     // [rows][768]: cols 0..511 = h1, 512..767 = dcoef pre-act
__device__ float g_h2[ROWS*NH];
__device__ float g_dh[ROWS*NF];
__device__ float g_dc[ROWS];
__device__ float g_cbe[NB*NCAT];       // merged bias: [cb | df_b1]
__device__ float g_k [6][ROWS*NF];
// ---------------- CSR for sparse Laplacian -----------------------------------
__device__ int   g_cnt[NN];
__device__ int   g_rp [NN+1];
__device__ int   g_cur[NN];
__device__ int   g_cidx[NE];
__device__ float g_wv [NE];
// ---------------- bf16 split operands (B-side natural [K][N]) ----------------
__device__ __nv_bfloat16 g_wce[NF*NCAT], g_wcl[NF*NCAT];   // [W1_state | df_w1]
__device__ __nv_bfloat16 g_w2h[NH*NH],  g_w2l[NH*NH];      // W2 [H][H]
__device__ __nv_bfloat16 g_w3h[NH*NF],  g_w3l[NH*NF];      // W3 [H][F]
__device__ __nv_bfloat16 g_yh[ROWS*NF], g_yl[ROWS*NF];     // yin split (A side)
__device__ __nv_bfloat16 g_ah[ROWS*NH], g_al[ROWS*NH];     // h1/h2 split (A side)

// ---------------- graph prep --------------------------------------------------
__global__ void deg_init_k(float* deg, int* cnt){
    int i = blockIdx.x*blockDim.x + threadIdx.x;
    if (i < NN){ deg[i] = 1.0f; cnt[i] = 0; }
}
__global__ void edge_k(const float* __restrict__ ea, const int* __restrict__ ei,
                       const float* __restrict__ w1, const float* __restrict__ b1,
                       const float* __restrict__ w2, const float* __restrict__ b2,
                       float* __restrict__ ew, float* __restrict__ deg,
                       int* __restrict__ cnt){
    int e = blockIdx.x*blockDim.x + threadIdx.x;
    if (e >= NE) return;
    float a = ea[e];
    float s = b2[0];
#pragma unroll
    for (int j = 0; j < 32; j++){
        float h = fmaxf(fmaf(a, w1[j], b1[j]), 0.0f);
        s = fmaf(h, w2[j], s);
    }
    ew[e] = 1.0f/(1.0f + expf(-s));
    atomicAdd(&deg[ei[NE + e]], 1.0f);     // unweighted degree at col (+self below)
    atomicAdd(&cnt[ei[e]], 1);             // CSR row count
}
// exclusive scan of cnt -> rp, init cursor (single block; once per launch)
__global__ void scan_k(const int* __restrict__ cnt, int* __restrict__ rp,
                       int* __restrict__ cur){
    __shared__ int s[NN];
    int t = threadIdx.x;                   // 1024 threads, 2 elems each
    s[t] = cnt[t]; s[t + 1024] = cnt[t + 1024];
    __syncthreads();
    if (t == 0){
        int run = 0;
#pragma unroll 8
        for (int i = 0; i < NN; i++){ int v = s[i]; s[i] = run; run += v; }
        rp[NN] = run;
    }
    __syncthreads();
    rp[t] = s[t];  rp[t + 1024] = s[t + 1024];
    cur[t] = s[t]; cur[t + 1024] = s[t + 1024];
}
__global__ void fill_k(const int* __restrict__ ei, const float* __restrict__ ew,
                       const float* __restrict__ deg, int* __restrict__ cur,
                       int* __restrict__ cidx, float* __restrict__ wv){
    int e = blockIdx.x*blockDim.x + threadIdx.x;
    if (e >= NE) return;
    int r = ei[e], c = ei[NE + e];
    int p = atomicAdd(&cur[r], 1);
    cidx[p] = c;
    wv[p] = rsqrtf(deg[r]) * ew[e] * rsqrtf(deg[c]);
}
// merged bias: [b][0..511] = b1 + ctx@W1_ctx ; [b][512..767] = df_b1
__global__ void ctxbias_k(const float* __restrict__ ctx, const float* __restrict__ w1,
                          const float* __restrict__ b1, const float* __restrict__ dfb1,
                          float* __restrict__ cbe){
    int h = blockIdx.x*blockDim.x + threadIdx.x;   // [0,768)
    int b = blockIdx.y;
    float s;
    if (h < NH){
        s = b1[h];
#pragma unroll 4
        for (int f = 0; f < NF; f++)
            s = fmaf(ctx[b*NF + f], w1[(size_t)(NF + f)*NH + h], s);
    } else {
        s = dfb1[h - NH];
    }
    cbe[b*NCAT + h] = s;
}
// concat-split of [W1_state | df_w1] into [K=256][768]
__global__ void catsplit_k(const float* __restrict__ w1, const float* __restrict__ dw,
                           __nv_bfloat16* __restrict__ hi, __nv_bfloat16* __restrict__ lo){
    int idx = blockIdx.x*blockDim.x + threadIdx.x;     // NF*NCAT
    int k = idx / NCAT, n = idx - k*NCAT;
    float v = (n < NH) ? w1[(size_t)k*NH + n] : dw[(size_t)k*NDF + (n - NH)];
    __nv_bfloat16 h = __float2bfloat16(v);
    hi[idx] = h;
    lo[idx] = __float2bfloat16(v - __bfloat162float(h));
}

// ---------------- split -------------------------------------------------------
__global__ void split_k(const float* __restrict__ x, __nv_bfloat16* __restrict__ hi,
                        __nv_bfloat16* __restrict__ lo, int n){
    int i = blockIdx.x*blockDim.x + threadIdx.x;
    if (i >= n) return;
    float v = x[i];
    __nv_bfloat16 h = __float2bfloat16(v);
    hi[i] = h;
    lo[i] = __float2bfloat16(v - __bfloat162float(h));
}

// ---------------- elementwise / small kernels --------------------------------
// layernorm(cols 0..511 of row stride ld) + relu -> split bf16
__global__ void ln_relu_split_k(const float* __restrict__ h, int ld,
                                const float* __restrict__ g, const float* __restrict__ b,
                                __nv_bfloat16* __restrict__ oh, __nv_bfloat16* __restrict__ ol){
    __shared__ float red[2][8];
    int r = blockIdx.x;
    const float* row = h + (size_t)r*ld;
    int t = threadIdx.x;                   // 256 threads, 2 elems (NH=512)
    float v0 = row[t], v1 = row[t + 256];
    float s  = v0 + v1;
    float ss = v0*v0 + v1*v1;
#pragma unroll
    for (int o = 16; o; o >>= 1){
        s  += __shfl_xor_sync(0xffffffffu, s,  o);
        ss += __shfl_xor_sync(0xffffffffu, ss, o);
    }
    if ((t & 31) == 0){ red[0][t>>5] = s; red[1][t>>5] = ss; }
    __syncthreads();
    float tot = 0.f, tot2 = 0.f;
#pragma unroll
    for (int i = 0; i < 8; i++){ tot += red[0][i]; tot2 += red[1][i]; }
    float mu  = tot  * (1.0f/NH);
    float var = tot2 * (1.0f/NH) - mu*mu;
    float is  = rsqrtf(var + 1e-5f);
    float o0 = fmaxf(fmaf((v0-mu)*is, g[t],       b[t]),       0.0f);
    float o1 = fmaxf(fmaf((v1-mu)*is, g[t + 256], b[t + 256]), 0.0f);
    size_t base = (size_t)r*NH;
    __nv_bfloat16 h0 = __float2bfloat16(o0), h1 = __float2bfloat16(o1);
    oh[base + t]       = h0;
    ol[base + t]       = __float2bfloat16(o0 - __bfloat162float(h0));
    oh[base + t + 256] = h1;
    ol[base + t + 256] = __float2bfloat16(o1 - __bfloat162float(h1));
}
// dcoef from cols 512..767 of h1e (relu applied here)
__global__ void dcoef_k(const float* __restrict__ h1e, const float* __restrict__ w2,
                        const float* __restrict__ b2, float* __restrict__ dc){
    __shared__ float red[8];
    int r = blockIdx.x;
    int t = threadIdx.x;                   // 256 threads = NDF
    float s = fmaxf(h1e[(size_t)r*NCAT + NH + t], 0.0f) * w2[t];
#pragma unroll
    for (int o = 16; o; o >>= 1) s += __shfl_xor_sync(0xffffffffu, s, o);
    if ((t & 31) == 0) red[t>>5] = s;
    __syncthreads();
    if (t == 0){
        float tot = 0.f;
#pragma unroll
        for (int i = 0; i < 8; i++) tot += red[i];
        dc[r] = 1.0f/(1.0f + expf(-(tot + b2[0])));
    }
}
__global__ void combine_k(float* __restrict__ out, const float* __restrict__ y,
                          __nv_bfloat16* __restrict__ oh, __nv_bfloat16* __restrict__ ol,
                          float dt, int nk,
                          float c0, float c1, float c2, float c3, float c4, float c5){
    int idx = blockIdx.x*blockDim.x + threadIdx.x;
    if (idx >= ROWS*NF) return;
    float c[6] = {c0, c1, c2, c3, c4, c5};
    float v = y[idx];
    for (int i = 0; i < nk; i++) v = fmaf(dt*c[i], g_k[i][idx], v);
    out[idx] = v;
    __nv_bfloat16 h = __float2bfloat16(v);
    oh[idx] = h;
    ol[idx] = __float2bfloat16(v - __bfloat162float(h));
}

// ---------------- sparse Laplacian apply + epilogue ---------------------------
// k[b,r,f] = dh[b,r,f] - dc[b,r] * ( (1-1/deg[r])*y[b,r,f] - sum_e w_e*y[b,c_e,f] )
#define MAXE 512
__global__ __launch_bounds__(256) void spmm_k(
    const float* __restrict__ y, const float* __restrict__ dh,
    const float* __restrict__ dc, const float* __restrict__ deg,
    const int* __restrict__ rp, const int* __restrict__ cidx,
    const float* __restrict__ wv, float* __restrict__ kout)
{
    __shared__ int   scol[MAXE];
    __shared__ float sw[MAXE];
    const int r = blockIdx.x;
    const int f = threadIdx.x;             // 256 = NF
    const int p0 = rp[r], cnt = rp[r+1] - p0;
    const float coef = 1.0f - 1.0f/deg[r];

    float acc[NB];
#pragma unroll
    for (int b = 0; b < NB; b++)
        acc[b] = coef * y[(size_t)((b<<11) + r)*NF + f];

    for (int base = 0; base < cnt; base += MAXE){
        const int m = min(MAXE, cnt - base);
        __syncthreads();
        for (int i = f; i < m; i += 256){
            scol[i] = cidx[p0 + base + i];
            sw[i]   = wv [p0 + base + i];
        }
        __syncthreads();
#pragma unroll
        for (int b = 0; b < NB; b++){
            const float* yb = y + ((size_t)b << 11)*NF;
            float s = 0.0f;
#pragma unroll 4
            for (int e = 0; e < m; e++)
                s = fmaf(sw[e], yb[(size_t)scol[e]*NF + f], s);
            acc[b] -= s;
        }
    }
#pragma unroll
    for (int b = 0; b < NB; b++){
        const size_t row = (size_t)((b<<11) + r);
        kout[row*NF + f] = dh[row*NF + f] - dc[row]*acc[b];
    }
}

// ---------------- split-bf16 tensor-core GEMM (mma.sync + ldmatrix) ----------
__device__ __forceinline__ uint32_t smem_u32(const void* p){
    uint32_t a;
    asm("{ .reg .u64 t; cvta.to.shared.u64 t, %1; cvt.u32.u64 %0, t; }" : "=r"(a) : "l"(p));
    return a;
}
#define MMA16816(d, a, b) \
    asm volatile("mma.sync.aligned.m16n8k16.row.col.f32.bf16.bf16.f32 " \
        "{%0,%1,%2,%3}, {%4,%5,%6,%7}, {%8,%9}, {%0,%1,%2,%3};" \
        : "+f"((d)[0]),"+f"((d)[1]),"+f"((d)[2]),"+f"((d)[3]) \
        : "r"((a)[0]),"r"((a)[1]),"r"((a)[2]),"r"((a)[3]), \
          "r"((b)[0]),"r"((b)[1]))
#define LDSM4(r0,r1,r2,r3,a) \
    asm volatile("ldmatrix.sync.aligned.m8n8.x4.shared.b16 {%0,%1,%2,%3}, [%4];" \
        : "=r"(r0),"=r"(r1),"=r"(r2),"=r"(r3) : "r"(a))
#define LDSM4T(r0,r1,r2,r3,a) \
    asm volatile("ldmatrix.sync.aligned.m8n8.x4.trans.shared.b16 {%0,%1,%2,%3}, [%4];" \
        : "=r"(r0),"=r"(r1),"=r"(r2),"=r"(r3) : "r"(a))

// D[m,n] = sum_k A[m,k]*B[k,n] + bias[(m>>11)*bstride + n]
// A = Ah+Al [M,K] row-major, B = Bh+Bl [K,N] row-major, lo*lo dropped.
// BM=128, BN=64, BK=32; 8 warps (4m x 2n).
__global__ __launch_bounds__(256) void mmagemm_k(
    const __nv_bfloat16* __restrict__ Ah, const __nv_bfloat16* __restrict__ Al,
    const __nv_bfloat16* __restrict__ Bh, const __nv_bfloat16* __restrict__ Bl,
    int ldb,
    const float* __restrict__ bias, int bstride,
    float* __restrict__ C, int Nt, int K)
{
    constexpr int LDSA = 40;
    constexpr int LDSB = 72;
    extern __shared__ __nv_bfloat16 smem[];
    __nv_bfloat16* sAh = smem;
    __nv_bfloat16* sAl = sAh + 2*128*LDSA;
    __nv_bfloat16* sBh = sAl + 2*128*LDSA;
    __nv_bfloat16* sBl = sBh + 2*32*LDSB;

    const int tid  = threadIdx.x;
    const int wid  = tid >> 5, lane = tid & 31;
    const int wm   = wid >> 1, wn = wid & 1;
    const int g    = lane >> 2, tig = lane & 3;
    const int m0   = blockIdx.y << 7;
    const int n0   = blockIdx.x << 6;

    const uint32_t uAh = smem_u32(sAh), uAl = smem_u32(sAl);
    const uint32_t uBh = smem_u32(sBh), uBl = smem_u32(sBl);
    const int l7 = lane & 7, l8 = (lane >> 3) & 1, l16 = lane >> 4;
    const uint32_t aoff0 = (uint32_t)((wm*32 + l7 + l8*8)*LDSA + l16*8)*2;
    const uint32_t aoff1 = aoff0 + 16*LDSA*2;
    const uint32_t boff0 = (uint32_t)((l7 + l8*8)*LDSB + wn*32 + l16*8)*2;
    const uint32_t boff1 = boff0 + 16*2;

    const int arow = tid >> 1, acol = (tid & 1) << 4;
    const int brow = tid >> 3, bcol = (tid & 7) << 3;
    const __nv_bfloat16* pAh = Ah + (size_t)(m0 + arow)*K + acol;
    const __nv_bfloat16* pAl = Al + (size_t)(m0 + arow)*K + acol;
    const __nv_bfloat16* pBh = Bh + (size_t)brow*ldb + n0 + bcol;
    const __nv_bfloat16* pBl = Bl + (size_t)brow*ldb + n0 + bcol;

    float acc[2][4][4];
#pragma unroll
    for (int i = 0; i < 2; i++)
#pragma unroll
        for (int j = 0; j < 4; j++)
#pragma unroll
            for (int q = 0; q < 4; q++) acc[i][j][q] = 0.0f;

    uint4 rah0 = *(const uint4*)(pAh);
    uint4 rah1 = *(const uint4*)(pAh + 8);
    uint4 ral0 = *(const uint4*)(pAl);
    uint4 ral1 = *(const uint4*)(pAl + 8);
    uint4 rbh  = *(const uint4*)(pBh);
    uint4 rbl  = *(const uint4*)(pBl);
    *(uint4*)&sAh[arow*LDSA + acol]     = rah0;
    *(uint4*)&sAh[arow*LDSA + acol + 8] = rah1;
    *(uint4*)&sAl[arow*LDSA + acol]     = ral0;
    *(uint4*)&sAl[arow*LDSA + acol + 8] = ral1;
    *(uint4*)&sBh[brow*LDSB + bcol]     = rbh;
    *(uint4*)&sBl[brow*LDSB + bcol]     = rbl;
    __syncthreads();

    const int nkt = K >> 5;
    for (int kt = 0; kt < nkt; kt++){
        const int cb = kt & 1;
        if (kt + 1 < nkt){
            const int k0 = (kt + 1) << 5;
            rah0 = *(const uint4*)(pAh + k0);
            rah1 = *(const uint4*)(pAh + k0 + 8);
            ral0 = *(const uint4*)(pAl + k0);
            ral1 = *(const uint4*)(pAl + k0 + 8);
            rbh  = *(const uint4*)(pBh + (size_t)k0*ldb);
            rbl  = *(const uint4*)(pBl + (size_t)k0*ldb);
        }
        const uint32_t oa = cb ? (uint32_t)(128*LDSA*2) : 0u;
        const uint32_t ob = cb ? (uint32_t)(32*LDSB*2)  : 0u;
#pragma unroll
        for (int kk = 0; kk < 2; kk++){
            const uint32_t ka = oa + (uint32_t)kk*16*2;
            const uint32_t kb = ob + (uint32_t)kk*16*LDSB*2;
            uint32_t afh[2][4], afl[2][4], bfh[4][2], bfl[4][2];
            LDSM4 (afh[0][0],afh[0][1],afh[0][2],afh[0][3], uAh + aoff0 + ka);
            LDSM4 (afh[1][0],afh[1][1],afh[1][2],afh[1][3], uAh + aoff1 + ka);
            LDSM4 (afl[0][0],afl[0][1],afl[0][2],afl[0][3], uAl + aoff0 + ka);
            LDSM4 (afl[1][0],afl[1][1],afl[1][2],afl[1][3], uAl + aoff1 + ka);
            LDSM4T(bfh[0][0],bfh[0][1],bfh[1][0],bfh[1][1], uBh + boff0 + kb);
            LDSM4T(bfh[2][0],bfh[2][1],bfh[3][0],bfh[3][1], uBh + boff1 + kb);
            LDSM4T(bfl[0][0],bfl[0][1],bfl[1][0],bfl[1][1], uBl + boff0 + kb);
            LDSM4T(bfl[2][0],bfl[2][1],bfl[3][0],bfl[3][1], uBl + boff1 + kb);
#pragma unroll
            for (int i = 0; i < 2; i++)
#pragma unroll
                for (int j = 0; j < 4; j++){
                    MMA16816(acc[i][j], afh[i], bfh[j]);
                    MMA16816(acc[i][j], afh[i], bfl[j]);
                    MMA16816(acc[i][j], afl[i], bfh[j]);
                }
        }
        if (kt + 1 < nkt){
            const int nb = (kt + 1) & 1;
            *(uint4*)&sAh[nb*128*LDSA + arow*LDSA + acol]     = rah0;
            *(uint4*)&sAh[nb*128*LDSA + arow*LDSA + acol + 8] = rah1;
            *(uint4*)&sAl[nb*128*LDSA + arow*LDSA + acol]     = ral0;
            *(uint4*)&sAl[nb*128*LDSA + arow*LDSA + acol + 8] = ral1;
            *(uint4*)&sBh[nb*32*LDSB + brow*LDSB + bcol]      = rbh;
            *(uint4*)&sBl[nb*32*LDSB + brow*LDSB + bcol]      = rbl;
            __syncthreads();
        }
    }

    const float* bp = bias + (size_t)(m0 >> 11)*bstride;
#pragma unroll
    for (int i = 0; i < 2; i++){
        const int ra = m0 + wm*32 + i*16 + g;
#pragma unroll
        for (int j = 0; j < 4; j++){
            const int col = n0 + wn*32 + j*8 + tig*2;
            const float b0 = bp[col], b1 = bp[col+1];
            float2 v0 = make_float2(acc[i][j][0] + b0, acc[i][j][1] + b1);
            float2 v1 = make_float2(acc[i][j][2] + b0, acc[i][j][3] + b1);
            *(float2*)&C[(size_t)ra*Nt + col]     = v0;
            *(float2*)&C[(size_t)(ra+8)*Nt + col] = v1;
        }
    }
}

// ---------------- host --------------------------------------------------------
static void* sym_addr(const void* s){
    void* p = nullptr;
    cudaGetSymbolAddress(&p, s);
    return p;
}

extern "C" void kernel_launch(void* const* d_in, const int* in_sizes, int n_in,
                              void* d_out, int out_size)
{
    const float* state = (const float*)d_in[0];
    const float* ctx   = (const float*)d_in[1];
    const float* ea    = (const float*)d_in[2];
    const int*   ei    = (const int*)  d_in[3];
    const float* ew_w1 = (const float*)d_in[4];
    const float* ew_b1 = (const float*)d_in[5];
    const float* ew_w2 = (const float*)d_in[6];
    const float* ew_b2 = (const float*)d_in[7];
    const float* td_w1 = (const float*)d_in[8];
    const float* td_b1 = (const float*)d_in[9];
    const float* ln1_g = (const float*)d_in[10];
    const float* ln1_b = (const float*)d_in[11];
    const float* td_w2 = (const float*)d_in[12];
    const float* td_b2 = (const float*)d_in[13];
    const float* ln2_g = (const float*)d_in[14];
    const float* ln2_b = (const float*)d_in[15];
    const float* td_w3 = (const float*)d_in[16];
    const float* td_b3 = (const float*)d_in[17];
    const float* df_w1 = (const float*)d_in[18];
    const float* df_b1 = (const float*)d_in[19];
    const float* df_w2 = (const float*)d_in[20];
    const float* df_b2 = (const float*)d_in[21];

    float* deg  = (float*)sym_addr(g_deg);
    float* ew   = (float*)sym_addr(g_ew);
    float* y    = (float*)sym_addr(g_y);
    float* yi   = (float*)sym_addr(g_yi);
    float* h1e  = (float*)sym_addr(g_h1e);
    float* h2   = (float*)sym_addr(g_h2);
    float* dh   = (float*)sym_addr(g_dh);
    float* dc   = (float*)sym_addr(g_dc);
    float* cbe  = (float*)sym_addr(g_cbe);
    float* kbuf = (float*)sym_addr(g_k);
    int*   cnt  = (int*)  sym_addr(g_cnt);
    int*   rp   = (int*)  sym_addr(g_rp);
    int*   cur  = (int*)  sym_addr(g_cur);
    int*   cidx = (int*)  sym_addr(g_cidx);
    float* wv   = (float*)sym_addr(g_wv);
    __nv_bfloat16* wce = (__nv_bfloat16*)sym_addr(g_wce);
    __nv_bfloat16* wcl = (__nv_bfloat16*)sym_addr(g_wcl);
    __nv_bfloat16* w2h = (__nv_bfloat16*)sym_addr(g_w2h);
    __nv_bfloat16* w2l = (__nv_bfloat16*)sym_addr(g_w2l);
    __nv_bfloat16* w3h = (__nv_bfloat16*)sym_addr(g_w3h);
    __nv_bfloat16* w3l = (__nv_bfloat16*)sym_addr(g_w3l);
    __nv_bfloat16* yh  = (__nv_bfloat16*)sym_addr(g_yh);
    __nv_bfloat16* yl  = (__nv_bfloat16*)sym_addr(g_yl);
    __nv_bfloat16* ah  = (__nv_bfloat16*)sym_addr(g_ah);
    __nv_bfloat16* al  = (__nv_bfloat16*)sym_addr(g_al);

    const int SMEM = (2*2*128*40 + 2*2*32*72) * 2;   // 59392 B
    cudaFuncSetAttribute(mmagemm_k, cudaFuncAttributeMaxDynamicSharedMemorySize, SMEM);

    // ---- graph prep: edge MLP, degrees, CSR (once per launch) ----
    deg_init_k<<<(NN + 255)/256, 256>>>(deg, cnt);
    edge_k<<<NE/256, 256>>>(ea, ei, ew_w1, ew_b1, ew_w2, ew_b2, ew, deg, cnt);
    scan_k<<<1, 1024>>>(cnt, rp, cur);
    fill_k<<<NE/256, 256>>>(ei, ew, deg, cur, cidx, wv);
    // weights: merged [W1_state | df_w1] + W2 + W3 (natural [K][N] layout)
    catsplit_k<<<(NF*NCAT)/256, 256>>>(td_w1, df_w1, wce, wcl);
    split_k<<<(NH*NH)/256, 256>>>(td_w2, w2h, w2l, NH*NH);
    split_k<<<(NH*NF)/256, 256>>>(td_w3, w3h, w3l, NH*NF);
    ctxbias_k<<<dim3(NCAT/128, NB), 128>>>(ctx, td_w1, td_b1, df_b1, cbe);

    cudaMemcpyAsync(y, state, sizeof(float)*ROWS*NF, cudaMemcpyDeviceToDevice, 0);
    split_k<<<(ROWS*NF)/256, 256>>>(y, yh, yl, ROWS*NF);

    // invariant: g_yh/g_yl always hold split(yin) when eval_f runs
    auto eval_f = [&](const float* yin, int ki){
        // merged layer1 + dcoef preact: yin @ [W1_state|df_w1] + [cb|df_b1]
        mmagemm_k<<<dim3(NCAT/64, ROWS/128), 256, SMEM>>>(
            yh, yl, wce, wcl, NCAT, cbe, NCAT, h1e, NCAT, NF);
        ln_relu_split_k<<<ROWS, 256>>>(h1e, NCAT, ln1_g, ln1_b, ah, al);
        dcoef_k<<<ROWS, 256>>>(h1e, df_w2, df_b2, dc);
        mmagemm_k<<<dim3(NH/64, ROWS/128), 256, SMEM>>>(
            ah, al, w2h, w2l, NH, td_b2, 0, h2, NH, NH);
        ln_relu_split_k<<<ROWS, 256>>>(h2, NH, ln2_g, ln2_b, ah, al);
        mmagemm_k<<<dim3(NF/64, ROWS/128), 256, SMEM>>>(
            ah, al, w3h, w3l, NF, td_b3, 0, dh, NF, NH);
        // k = dh - dcoef * (L @ y)  via CSR SpMM (exact fp32)
        spmm_k<<<NN, 256>>>(yin, dh, dc, deg, rp, cidx, wv,
                            kbuf + (size_t)ki*ROWS*NF);
    };

    const float dt = 0.25f;   // (T1-T0)/N_STEPS
    const int nblk = (ROWS*NF)/256;
    for (int s = 0; s < 4; s++){
        // k7 of dopri5 is dead (b7 == 0, no FSAL reuse) -> 6 stages only
        eval_f(y, 0);
        combine_k<<<nblk, 256>>>(yi, y, yh, yl, dt, 1,
            (float)(1.0/5.0), 0.f, 0.f, 0.f, 0.f, 0.f);
        eval_f(yi, 1);
        combine_k<<<nblk, 256>>>(yi, y, yh, yl, dt, 2,
            (float)(3.0/40.0), (float)(9.0/40.0), 0.f, 0.f, 0.f, 0.f);
        eval_f(yi, 2);
        combine_k<<<nblk, 256>>>(yi, y, yh, yl, dt, 3,
            (float)(44.0/45.0), (float)(-56.0/15.0), (float)(32.0/9.0), 0.f, 0.f, 0.f);
        eval_f(yi, 3);
        combine_k<<<nblk, 256>>>(yi, y, yh, yl, dt, 4,
            (float)(19372.0/6561.0), (float)(-25360.0/2187.0),
            (float)(64448.0/6561.0), (float)(-212.0/729.0), 0.f, 0.f);
        eval_f(yi, 4);
        combine_k<<<nblk, 256>>>(yi, y, yh, yl, dt, 5,
            (float)(9017.0/3168.0), (float)(-355.0/33.0),
            (float)(46732.0/5247.0), (float)(49.0/176.0),
            (float)(-5103.0/18656.0), 0.f);
        eval_f(yi, 5);
        combine_k<<<nblk, 256>>>(y, y, yh, yl, dt, 6,
            (float)(35.0/384.0), 0.f, (float)(500.0/1113.0),
            (float)(125.0/192.0), (float)(-2187.0/6784.0), (float)(11.0/84.0));
    }

    cudaMemcpyAsync(d_out, y, sizeof(float)*ROWS*NF, cudaMemcpyDeviceToDevice, 0);
}

// round 10
// speedup vs baseline: 3.8058x; 1.1113x over previous
#include <cuda_runtime.h>
#include <cuda_bf16.h>
#include <math.h>
#include <stdint.h>

#define NB 4
#define NN 2048
#define NF 256
#define NH 512
#define NDF 256          /* H/2 */
#define NE 65536
#define ROWS (NB*NN)     /* 8192 */
#define NCAT (NH + NDF)  /* 768 */
#define RN (ROWS*NF)

// ---------------- fp32 scratch ----------------------------------------------
__device__ float g_deg[NN];
__device__ float g_ew[NE];
__device__ float g_y [RN];
__device__ float g_ya[RN];
__device__ float g_yb[RN];
__device__ float g_h1e[ROWS*NCAT];
__device__ float g_h2[ROWS*NH];
__device__ float g_dh[RN];
__device__ float g_dc[ROWS];
__device__ float g_cbe[NB*NCAT];
__device__ float g_k [6][RN];
// ---------------- CSR ---------------------------------------------------------
__device__ int   g_cnt[NN];
__device__ int   g_rp [NN+1];
__device__ int   g_cur[NN];
__device__ int   g_cidx[NE];
__device__ float g_wv [NE];
// ---------------- bf16 split operands ----------------------------------------
__device__ __nv_bfloat16 g_wce[NF*NCAT], g_wcl[NF*NCAT];   // [W1_state | df_w1]
__device__ __nv_bfloat16 g_w2h[NH*NH],  g_w2l[NH*NH];
__device__ __nv_bfloat16 g_w3h[NH*NF],  g_w3l[NH*NF];
__device__ __nv_bfloat16 g_yh[RN], g_yl[RN];               // split(yin)
__device__ __nv_bfloat16 g_ah[ROWS*NH], g_al[ROWS*NH];

// ---------------- graph prep --------------------------------------------------
__global__ void deg_init_k(float* deg, int* cnt){
    int i = blockIdx.x*blockDim.x + threadIdx.x;
    if (i < NN){ deg[i] = 1.0f; cnt[i] = 0; }
}
__global__ void edge_k(const float* __restrict__ ea, const int* __restrict__ ei,
                       const float* __restrict__ w1, const float* __restrict__ b1,
                       const float* __restrict__ w2, const float* __restrict__ b2,
                       float* __restrict__ ew, float* __restrict__ deg,
                       int* __restrict__ cnt){
    int e = blockIdx.x*blockDim.x + threadIdx.x;
    if (e >= NE) return;
    float a = ea[e];
    float s = b2[0];
#pragma unroll
    for (int j = 0; j < 32; j++){
        float h = fmaxf(fmaf(a, w1[j], b1[j]), 0.0f);
        s = fmaf(h, w2[j], s);
    }
    ew[e] = 1.0f/(1.0f + expf(-s));
    atomicAdd(&deg[ei[NE + e]], 1.0f);
    atomicAdd(&cnt[ei[e]], 1);
}
__global__ void scan_k(const int* __restrict__ cnt, int* __restrict__ rp,
                       int* __restrict__ cur){
    __shared__ int s[NN];
    int t = threadIdx.x;
    s[t] = cnt[t]; s[t + 1024] = cnt[t + 1024];
    __syncthreads();
    if (t == 0){
        int run = 0;
#pragma unroll 8
        for (int i = 0; i < NN; i++){ int v = s[i]; s[i] = run; run += v; }
        rp[NN] = run;
    }
    __syncthreads();
    rp[t] = s[t];  rp[t + 1024] = s[t + 1024];
    cur[t] = s[t]; cur[t + 1024] = s[t + 1024];
}
__global__ void fill_k(const int* __restrict__ ei, const float* __restrict__ ew,
                       const float* __restrict__ deg, int* __restrict__ cur,
                       int* __restrict__ cidx, float* __restrict__ wv){
    int e = blockIdx.x*blockDim.x + threadIdx.x;
    if (e >= NE) return;
    int r = ei[e], c = ei[NE + e];
    int p = atomicAdd(&cur[r], 1);
    cidx[p] = c;
    wv[p] = rsqrtf(deg[r]) * ew[e] * rsqrtf(deg[c]);
}
__global__ void ctxbias_k(const float* __restrict__ ctx, const float* __restrict__ w1,
                          const float* __restrict__ b1, const float* __restrict__ dfb1,
                          float* __restrict__ cbe){
    int h = blockIdx.x*blockDim.x + threadIdx.x;
    int b = blockIdx.y;
    float s;
    if (h < NH){
        s = b1[h];
#pragma unroll 4
        for (int f = 0; f < NF; f++)
            s = fmaf(ctx[b*NF + f], w1[(size_t)(NF + f)*NH + h], s);
    } else {
        s = dfb1[h - NH];
    }
    cbe[b*NCAT + h] = s;
}
__global__ void catsplit_k(const float* __restrict__ w1, const float* __restrict__ dw,
                           __nv_bfloat16* __restrict__ hi, __nv_bfloat16* __restrict__ lo){
    int idx = blockIdx.x*blockDim.x + threadIdx.x;
    int k = idx / NCAT, n = idx - k*NCAT;
    float v = (n < NH) ? w1[(size_t)k*NH + n] : dw[(size_t)k*NDF + (n - NH)];
    __nv_bfloat16 h = __float2bfloat16(v);
    hi[idx] = h;
    lo[idx] = __float2bfloat16(v - __bfloat162float(h));
}
__global__ void split_k(const float* __restrict__ x, __nv_bfloat16* __restrict__ hi,
                        __nv_bfloat16* __restrict__ lo, int n){
    int i = blockIdx.x*blockDim.x + threadIdx.x;
    if (i >= n) return;
    float v = x[i];
    __nv_bfloat16 h = __float2bfloat16(v);
    hi[i] = h;
    lo[i] = __float2bfloat16(v - __bfloat162float(h));
}

// ---------------- fused LN(+relu+split) and optional dcoef --------------------
__global__ void ln_fused_k(const float* __restrict__ h, int ld,
                           const float* __restrict__ g, const float* __restrict__ b,
                           __nv_bfloat16* __restrict__ oh, __nv_bfloat16* __restrict__ ol,
                           const float* __restrict__ dw2, const float* __restrict__ db2,
                           float* __restrict__ dc, int do_dc){
    __shared__ float red[3][8];
    int r = blockIdx.x;
    const float* row = h + (size_t)r*ld;
    int t = threadIdx.x;                   // 256
    float v0 = row[t], v1 = row[t + 256];
    float s  = v0 + v1;
    float ss = v0*v0 + v1*v1;
    float d  = 0.0f;
    if (do_dc) d = fmaxf(row[NH + t], 0.0f) * dw2[t];
#pragma unroll
    for (int o = 16; o; o >>= 1){
        s  += __shfl_xor_sync(0xffffffffu, s,  o);
        ss += __shfl_xor_sync(0xffffffffu, ss, o);
        d  += __shfl_xor_sync(0xffffffffu, d,  o);
    }
    if ((t & 31) == 0){ red[0][t>>5] = s; red[1][t>>5] = ss; red[2][t>>5] = d; }
    __syncthreads();
    float tot = 0.f, tot2 = 0.f;
#pragma unroll
    for (int i = 0; i < 8; i++){ tot += red[0][i]; tot2 += red[1][i]; }
    float mu  = tot  * (1.0f/NH);
    float var = tot2 * (1.0f/NH) - mu*mu;
    float is  = rsqrtf(var + 1e-5f);
    float o0 = fmaxf(fmaf((v0-mu)*is, g[t],       b[t]),       0.0f);
    float o1 = fmaxf(fmaf((v1-mu)*is, g[t + 256], b[t + 256]), 0.0f);
    size_t base = (size_t)r*NH;
    __nv_bfloat16 h0 = __float2bfloat16(o0), h1 = __float2bfloat16(o1);
    oh[base + t]       = h0;
    ol[base + t]       = __float2bfloat16(o0 - __bfloat162float(h0));
    oh[base + t + 256] = h1;
    ol[base + t + 256] = __float2bfloat16(o1 - __bfloat162float(h1));
    if (do_dc && t == 0){
        float td = 0.f;
#pragma unroll
        for (int i = 0; i < 8; i++) td += red[2][i];
        dc[r] = 1.0f/(1.0f + expf(-(td + db2[0])));
    }
}

// ---------------- SpMM + RK combine (fused) -----------------------------------
// k_ki[b,r,f] = dh - dc*((1-1/deg)*yin[r] - sum w_e yin[c_e]); then
// out = ybase + sum_{j<=ki} dtc_j * k_j ; oh/ol = split(out).
#define MAXE 512
__global__ __launch_bounds__(256) void spmm_comb_k(
    const float* __restrict__ yin, const float* __restrict__ dh,
    const float* __restrict__ dc, const float* __restrict__ deg,
    const int* __restrict__ rp, const int* __restrict__ cidx,
    const float* __restrict__ wv,
    float* __restrict__ kbuf, int ki,
    const float* __restrict__ ybase, float* __restrict__ out,
    __nv_bfloat16* __restrict__ oh, __nv_bfloat16* __restrict__ ol,
    float c0, float c1, float c2, float c3, float c4, float c5)
{
    __shared__ int   scol[MAXE];
    __shared__ float sw[MAXE];
    const int r = blockIdx.x;
    const int f = threadIdx.x;             // 256 = NF
    const int p0 = rp[r], cnt = rp[r+1] - p0;
    const float coef = 1.0f - 1.0f/deg[r];
    const float dtc[6] = {c0, c1, c2, c3, c4, c5};

    float acc[NB];
#pragma unroll
    for (int b = 0; b < NB; b++)
        acc[b] = coef * yin[(size_t)((b<<11) + r)*NF + f];

    for (int base = 0; base < cnt; base += MAXE){
        const int m = min(MAXE, cnt - base);
        __syncthreads();
        for (int i = f; i < m; i += 256){
            scol[i] = cidx[p0 + base + i];
            sw[i]   = wv [p0 + base + i];
        }
        __syncthreads();
#pragma unroll
        for (int b = 0; b < NB; b++){
            const float* yb = yin + ((size_t)b << 11)*NF;
            float s = 0.0f;
#pragma unroll 4
            for (int e = 0; e < m; e++)
                s = fmaf(sw[e], yb[(size_t)scol[e]*NF + f], s);
            acc[b] -= s;
        }
    }
#pragma unroll
    for (int b = 0; b < NB; b++){
        const size_t row = (size_t)((b<<11) + r);
        const size_t idx = row*NF + f;
        float kval = dh[idx] - dc[row]*acc[b];
        kbuf[(size_t)ki*RN + idx] = kval;
        float v = ybase[idx];
        for (int j = 0; j < ki; j++)
            v = fmaf(dtc[j], kbuf[(size_t)j*RN + idx], v);
        v = fmaf(dtc[ki], kval, v);
        out[idx] = v;
        __nv_bfloat16 h = __float2bfloat16(v);
        oh[idx] = h;
        ol[idx] = __float2bfloat16(v - __bfloat162float(h));
    }
}

// ---------------- split-bf16 tensor-core GEMM, BM=128 BN=128 BK=32 -----------
__device__ __forceinline__ uint32_t smem_u32(const void* p){
    uint32_t a;
    asm("{ .reg .u64 t; cvta.to.shared.u64 t, %1; cvt.u32.u64 %0, t; }" : "=r"(a) : "l"(p));
    return a;
}
#define MMA16816(d, a, b) \
    asm volatile("mma.sync.aligned.m16n8k16.row.col.f32.bf16.bf16.f32 " \
        "{%0,%1,%2,%3}, {%4,%5,%6,%7}, {%8,%9}, {%0,%1,%2,%3};" \
        : "+f"((d)[0]),"+f"((d)[1]),"+f"((d)[2]),"+f"((d)[3]) \
        : "r"((a)[0]),"r"((a)[1]),"r"((a)[2]),"r"((a)[3]), \
          "r"((b)[0]),"r"((b)[1]))
#define LDSM4(r0,r1,r2,r3,a) \
    asm volatile("ldmatrix.sync.aligned.m8n8.x4.shared.b16 {%0,%1,%2,%3}, [%4];" \
        : "=r"(r0),"=r"(r1),"=r"(r2),"=r"(r3) : "r"(a))
#define LDSM4T(r0,r1,r2,r3,a) \
    asm volatile("ldmatrix.sync.aligned.m8n8.x4.trans.shared.b16 {%0,%1,%2,%3}, [%4];" \
        : "=r"(r0),"=r"(r1),"=r"(r2),"=r"(r3) : "r"(a))

// D[m,n] = sum_k A[m,k]*B[k,n] + bias[(m>>11)*bstride + n]
// A = Ah+Al [M,K] row-major, B = Bh+Bl [K,N] row-major (ldb), lo*lo dropped.
// 8 warps (4m x 2n), warp tile 32x64.
__global__ __launch_bounds__(256) void mmagemm_k(
    const __nv_bfloat16* __restrict__ Ah, const __nv_bfloat16* __restrict__ Al,
    const __nv_bfloat16* __restrict__ Bh, const __nv_bfloat16* __restrict__ Bl,
    int ldb,
    const float* __restrict__ bias, int bstride,
    float* __restrict__ C, int Nt, int K)
{
    constexpr int LDSA = 40;    // 5x16B: stride-5 mod 8 -> conflict-free LDSM
    constexpr int LDSB = 136;   // 17x16B: stride-17 mod 8 = 1 -> conflict-free LDSM.T
    extern __shared__ __nv_bfloat16 smem[];
    __nv_bfloat16* sAh = smem;                    // 2 x 128 x LDSA
    __nv_bfloat16* sAl = sAh + 2*128*LDSA;
    __nv_bfloat16* sBh = sAl + 2*128*LDSA;        // 2 x 32 x LDSB
    __nv_bfloat16* sBl = sBh + 2*32*LDSB;

    const int tid  = threadIdx.x;
    const int wid  = tid >> 5, lane = tid & 31;
    const int wm   = wid >> 1, wn = wid & 1;
    const int g    = lane >> 2, tig = lane & 3;
    const int m0   = blockIdx.y << 7;
    const int n0   = blockIdx.x << 7;

    const uint32_t uAh = smem_u32(sAh), uAl = smem_u32(sAl);
    const uint32_t uBh = smem_u32(sBh), uBl = smem_u32(sBl);
    const int l7 = lane & 7, l8 = (lane >> 3) & 1, l16 = lane >> 4;
    const uint32_t aoff0 = (uint32_t)((wm*32 + l7 + l8*8)*LDSA + l16*8)*2;
    const uint32_t aoff1 = aoff0 + 16*LDSA*2;
    uint32_t boff[4];
#pragma unroll
    for (int j2 = 0; j2 < 4; j2++)
        boff[j2] = (uint32_t)((l7 + l8*8)*LDSB + wn*64 + j2*16 + l16*8)*2;

    const int arow = tid >> 1, acol = (tid & 1) << 4;
    const int brow = tid >> 4, bcol = (tid & 15) << 3;
    const __nv_bfloat16* pAh = Ah + (size_t)(m0 + arow)*K + acol;
    const __nv_bfloat16* pAl = Al + (size_t)(m0 + arow)*K + acol;
    const __nv_bfloat16* pBh = Bh + (size_t)brow*ldb + n0 + bcol;
    const __nv_bfloat16* pBl = Bl + (size_t)brow*ldb + n0 + bcol;
    const size_t bstep = (size_t)16*ldb;

    float acc[2][8][4];
#pragma unroll
    for (int i = 0; i < 2; i++)
#pragma unroll
        for (int j = 0; j < 8; j++)
#pragma unroll
            for (int q = 0; q < 4; q++) acc[i][j][q] = 0.0f;

    uint4 rah0 = *(const uint4*)(pAh);
    uint4 rah1 = *(const uint4*)(pAh + 8);
    uint4 ral0 = *(const uint4*)(pAl);
    uint4 ral1 = *(const uint4*)(pAl + 8);
    uint4 rbh0 = *(const uint4*)(pBh);
    uint4 rbh1 = *(const uint4*)(pBh + bstep);
    uint4 rbl0 = *(const uint4*)(pBl);
    uint4 rbl1 = *(const uint4*)(pBl + bstep);
    *(uint4*)&sAh[arow*LDSA + acol]       = rah0;
    *(uint4*)&sAh[arow*LDSA + acol + 8]   = rah1;
    *(uint4*)&sAl[arow*LDSA + acol]       = ral0;
    *(uint4*)&sAl[arow*LDSA + acol + 8]   = ral1;
    *(uint4*)&sBh[brow*LDSB + bcol]       = rbh0;
    *(uint4*)&sBh[(brow+16)*LDSB + bcol]  = rbh1;
    *(uint4*)&sBl[brow*LDSB + bcol]       = rbl0;
    *(uint4*)&sBl[(brow+16)*LDSB + bcol]  = rbl1;
    __syncthreads();

    const int nkt = K >> 5;
    for (int kt = 0; kt < nkt; kt++){
        const int cb = kt & 1;
        if (kt + 1 < nkt){
            const int k0 = (kt + 1) << 5;
            rah0 = *(const uint4*)(pAh + k0);
            rah1 = *(const uint4*)(pAh + k0 + 8);
            ral0 = *(const uint4*)(pAl + k0);
            ral1 = *(const uint4*)(pAl + k0 + 8);
            rbh0 = *(const uint4*)(pBh + (size_t)k0*ldb);
            rbh1 = *(const uint4*)(pBh + (size_t)k0*ldb + bstep);
            rbl0 = *(const uint4*)(pBl + (size_t)k0*ldb);
            rbl1 = *(const uint4*)(pBl + (size_t)k0*ldb + bstep);
        }
        const uint32_t oa = cb ? (uint32_t)(128*LDSA*2) : 0u;
        const uint32_t ob = cb ? (uint32_t)(32*LDSB*2)  : 0u;
#pragma unroll
        for (int kk = 0; kk < 2; kk++){
            const uint32_t ka = oa + (uint32_t)kk*16*2;
            const uint32_t kb = ob + (uint32_t)kk*16*LDSB*2;
            uint32_t afh[2][4], afl[2][4], bfh[8][2], bfl[8][2];
            LDSM4 (afh[0][0],afh[0][1],afh[0][2],afh[0][3], uAh + aoff0 + ka);
            LDSM4 (afh[1][0],afh[1][1],afh[1][2],afh[1][3], uAh + aoff1 + ka);
            LDSM4 (afl[0][0],afl[0][1],afl[0][2],afl[0][3], uAl + aoff0 + ka);
            LDSM4 (afl[1][0],afl[1][1],afl[1][2],afl[1][3], uAl + aoff1 + ka);
#pragma unroll
            for (int j2 = 0; j2 < 4; j2++){
                LDSM4T(bfh[2*j2][0],bfh[2*j2][1],bfh[2*j2+1][0],bfh[2*j2+1][1],
                       uBh + boff[j2] + kb);
                LDSM4T(bfl[2*j2][0],bfl[2*j2][1],bfl[2*j2+1][0],bfl[2*j2+1][1],
                       uBl + boff[j2] + kb);
            }
#pragma unroll
            for (int i = 0; i < 2; i++)
#pragma unroll
                for (int j = 0; j < 8; j++){
                    MMA16816(acc[i][j], afh[i], bfh[j]);
                    MMA16816(acc[i][j], afh[i], bfl[j]);
                    MMA16816(acc[i][j], afl[i], bfh[j]);
                }
        }
        if (kt + 1 < nkt){
            const int nb = (kt + 1) & 1;
            *(uint4*)&sAh[nb*128*LDSA + arow*LDSA + acol]      = rah0;
            *(uint4*)&sAh[nb*128*LDSA + arow*LDSA + acol + 8]  = rah1;
            *(uint4*)&sAl[nb*128*LDSA + arow*LDSA + acol]      = ral0;
            *(uint4*)&sAl[nb*128*LDSA + arow*LDSA + acol + 8]  = ral1;
            *(uint4*)&sBh[nb*32*LDSB + brow*LDSB + bcol]       = rbh0;
            *(uint4*)&sBh[nb*32*LDSB + (brow+16)*LDSB + bcol]  = rbh1;
            *(uint4*)&sBl[nb*32*LDSB + brow*LDSB + bcol]       = rbl0;
            *(uint4*)&sBl[nb*32*LDSB + (brow+16)*LDSB + bcol]  = rbl1;
            __syncthreads();
        }
    }

    const float* bp = bias + (size_t)(m0 >> 11)*bstride;
#pragma unroll
    for (int i = 0; i < 2; i++){
        const int ra = m0 + wm*32 + i*16 + g;
#pragma unroll
        for (int j = 0; j < 8; j++){
            const int col = n0 + wn*64 + j*8 + tig*2;
            const float b0 = bp[col], b1 = bp[col+1];
            float2 v0 = make_float2(acc[i][j][0] + b0, acc[i][j][1] + b1);
            float2 v1 = make_float2(acc[i][j][2] + b0, acc[i][j][3] + b1);
            *(float2*)&C[(size_t)ra*Nt + col]     = v0;
            *(float2*)&C[(size_t)(ra+8)*Nt + col] = v1;
        }
    }
}

// ---------------- host --------------------------------------------------------
static void* sym_addr(const void* s){
    void* p = nullptr;
    cudaGetSymbolAddress(&p, s);
    return p;
}

extern "C" void kernel_launch(void* const* d_in, const int* in_sizes, int n_in,
                              void* d_out, int out_size)
{
    const float* state = (const float*)d_in[0];
    const float* ctx   = (const float*)d_in[1];
    const float* ea    = (const float*)d_in[2];
    const int*   ei    = (const int*)  d_in[3];
    const float* ew_w1 = (const float*)d_in[4];
    const float* ew_b1 = (const float*)d_in[5];
    const float* ew_w2 = (const float*)d_in[6];
    const float* ew_b2 = (const float*)d_in[7];
    const float* td_w1 = (const float*)d_in[8];
    const float* td_b1 = (const float*)d_in[9];
    const float* ln1_g = (const float*)d_in[10];
    const float* ln1_b = (const float*)d_in[11];
    const float* td_w2 = (const float*)d_in[12];
    const float* td_b2 = (const float*)d_in[13];
    const float* ln2_g = (const float*)d_in[14];
    const float* ln2_b = (const float*)d_in[15];
    const float* td_w3 = (const float*)d_in[16];
    const float* td_b3 = (const float*)d_in[17];
    const float* df_w1 = (const float*)d_in[18];
    const float* df_b1 = (const float*)d_in[19];
    const float* df_w2 = (const float*)d_in[20];
    const float* df_b2 = (const float*)d_in[21];

    float* deg  = (float*)sym_addr(g_deg);
    float* ew   = (float*)sym_addr(g_ew);
    float* y    = (float*)sym_addr(g_y);
    float* ya   = (float*)sym_addr(g_ya);
    float* yb   = (float*)sym_addr(g_yb);
    float* h1e  = (float*)sym_addr(g_h1e);
    float* h2   = (float*)sym_addr(g_h2);
    float* dh   = (float*)sym_addr(g_dh);
    float* dc   = (float*)sym_addr(g_dc);
    float* cbe  = (float*)sym_addr(g_cbe);
    float* kbuf = (float*)sym_addr(g_k);
    int*   cnt  = (int*)  sym_addr(g_cnt);
    int*   rp   = (int*)  sym_addr(g_rp);
    int*   cur  = (int*)  sym_addr(g_cur);
    int*   cidx = (int*)  sym_addr(g_cidx);
    float* wv   = (float*)sym_addr(g_wv);
    __nv_bfloat16* wce = (__nv_bfloat16*)sym_addr(g_wce);
    __nv_bfloat16* wcl = (__nv_bfloat16*)sym_addr(g_wcl);
    __nv_bfloat16* w2h = (__nv_bfloat16*)sym_addr(g_w2h);
    __nv_bfloat16* w2l = (__nv_bfloat16*)sym_addr(g_w2l);
    __nv_bfloat16* w3h = (__nv_bfloat16*)sym_addr(g_w3h);
    __nv_bfloat16* w3l = (__nv_bfloat16*)sym_addr(g_w3l);
    __nv_bfloat16* yh  = (__nv_bfloat16*)sym_addr(g_yh);
    __nv_bfloat16* yl  = (__nv_bfloat16*)sym_addr(g_yl);
    __nv_bfloat16* ah  = (__nv_bfloat16*)sym_addr(g_ah);
    __nv_bfloat16* al  = (__nv_bfloat16*)sym_addr(g_al);

    const int SMEM = (2*2*128*40 + 2*2*32*136) * 2;   // 75776 B
    cudaFuncSetAttribute(mmagemm_k, cudaFuncAttributeMaxDynamicSharedMemorySize, SMEM);

    // ---- graph prep (once per launch) ----
    deg_init_k<<<(NN + 255)/256, 256>>>(deg, cnt);
    edge_k<<<NE/256, 256>>>(ea, ei, ew_w1, ew_b1, ew_w2, ew_b2, ew, deg, cnt);
    scan_k<<<1, 1024>>>(cnt, rp, cur);
    fill_k<<<NE/256, 256>>>(ei, ew, deg, cur, cidx, wv);
    catsplit_k<<<(NF*NCAT)/256, 256>>>(td_w1, df_w1, wce, wcl);
    split_k<<<(NH*NH)/256, 256>>>(td_w2, w2h, w2l, NH*NH);
    split_k<<<(NH*NF)/256, 256>>>(td_w3, w3h, w3l, NH*NF);
    ctxbias_k<<<dim3(NCAT/128, NB), 128>>>(ctx, td_w1, td_b1, df_b1, cbe);

    cudaMemcpyAsync(y, state, sizeof(float)*RN, cudaMemcpyDeviceToDevice, 0);
    split_k<<<RN/256, 256>>>(y, yh, yl, RN);

    const float dt = 0.25f;   // (T1-T0)/N_STEPS

    // invariant: g_yh/g_yl always hold split(yin) when eval_f runs.
    // eval_f computes k_ki from yin, then fused-combines into `out` (+split).
    auto eval_f = [&](const float* yin, int ki, float* out,
                      float c0, float c1, float c2, float c3, float c4, float c5){
        mmagemm_k<<<dim3(NCAT/128, ROWS/128), 256, SMEM>>>(
            yh, yl, wce, wcl, NCAT, cbe, NCAT, h1e, NCAT, NF);
        ln_fused_k<<<ROWS, 256>>>(h1e, NCAT, ln1_g, ln1_b, ah, al,
                                  df_w2, df_b2, dc, 1);
        mmagemm_k<<<dim3(NH/128, ROWS/128), 256, SMEM>>>(
            ah, al, w2h, w2l, NH, td_b2, 0, h2, NH, NH);
        ln_fused_k<<<ROWS, 256>>>(h2, NH, ln2_g, ln2_b, ah, al,
                                  nullptr, nullptr, nullptr, 0);
        mmagemm_k<<<dim3(NF/128, ROWS/128), 256, SMEM>>>(
            ah, al, w3h, w3l, NF, td_b3, 0, dh, NF, NH);
        spmm_comb_k<<<NN, 256>>>(yin, dh, dc, deg, rp, cidx, wv,
                                 kbuf, ki, y, out, yh, yl,
                                 dt*c0, dt*c1, dt*c2, dt*c3, dt*c4, dt*c5);
    };

    for (int s = 0; s < 4; s++){
        // k7 of dopri5 is dead (b7 == 0, no FSAL reuse) -> 6 stages only.
        // yi ping-pong: out buffer never equals the cross-row-read yin buffer.
        eval_f(y,  0, ya, 1.f/5.f, 0.f, 0.f, 0.f, 0.f, 0.f);
        eval_f(ya, 1, yb, 3.f/40.f, 9.f/40.f, 0.f, 0.f, 0.f, 0.f);
        eval_f(yb, 2, ya, 44.f/45.f, -56.f/15.f, 32.f/9.f, 0.f, 0.f, 0.f);
        eval_f(ya, 3, yb, (float)(19372.0/6561.0), (float)(-25360.0/2187.0),
                          (float)(64448.0/6561.0), (float)(-212.0/729.0), 0.f, 0.f);
        eval_f(yb, 4, ya, (float)(9017.0/3168.0), (float)(-355.0/33.0),
                          (float)(46732.0/5247.0), (float)(49.0/176.0),
                          (float)(-5103.0/18656.0), 0.f);
        eval_f(ya, 5, y,  (float)(35.0/384.0), 0.f, (float)(500.0/1113.0),
                          (float)(125.0/192.0), (float)(-2187.0/6784.0),
                          (float)(11.0/84.0));
    }

    cudaMemcpyAsync(d_out, y, sizeof(float)*RN, cudaMemcpyDeviceToDevice, 0);
}